// round 8
// baseline (speedup 1.0000x reference)
#include <cuda_runtime.h>
#include <cuda_fp16.h>

#define B_   8
#define NX_  512
#define NR_  512
#define D_   256
#define H_   256

// Scratch (device globals — no allocation allowed anywhere)
__device__ __half   g_hXT[B_ * H_ * NX_];   // [b][h][x]  fp16, transposed
__device__ __half   g_hRT[B_ * H_ * NR_];   // [b][h][r]  fp16, transposed
__device__ float    g_S  [B_ * NR_ * NX_];  // [b][r][x]  scores -> attn in place
__device__ unsigned g_tile;                 // dynamic tile counter for score

__device__ __forceinline__ __half2 tanh2(__half2 x) {
    __half2 y;
    asm("tanh.approx.f16x2 %0, %1;"
        : "=r"(*reinterpret_cast<unsigned*>(&y))
        : "r"(*reinterpret_cast<unsigned*>(&x)));
    return y;
}

// ---------------------------------------------------------------------------
// Phase 1 (merged): hT[b][h][x] = sum_d W[h][d]*A[b][x][d] + bias[h], fp16 out.
// grid.z in [0,16): z<8 -> X -> g_hXT ; z>=8 -> ref -> g_hRT.
// Register-prefetch double buffering: LDG for chunk k+1 issues before the
// FFMA block of chunk k, hiding global latency behind ~1000 cyc of compute.
// ---------------------------------------------------------------------------
__global__ __launch_bounds__(256) void proj_kernel(const float* __restrict__ X,
                                                   const float* __restrict__ ref,
                                                   const float* __restrict__ W_X,
                                                   const float* __restrict__ b_X,
                                                   const float* __restrict__ W_ref,
                                                   const float* __restrict__ b_ref) {
    __shared__ float Ws[32][64];   // [k][h]
    __shared__ float As[32][64];   // [k][x]
    int tid = threadIdx.x;
    if (blockIdx.x == 0 && blockIdx.y == 0 && blockIdx.z == 0 && tid == 0)
        g_tile = 0u;

    int z = blockIdx.z;
    int b = z & 7;
    const float* A    = (z < 8) ? X     : ref;
    const float* W    = (z < 8) ? W_X   : W_ref;
    const float* bias = (z < 8) ? b_X   : b_ref;
    __half*      C    = (z < 8) ? g_hXT : g_hRT;

    const int K = D_;
    int tx = tid & 15, ty = tid >> 4;
    int x0 = blockIdx.x * 64, h0 = blockIdx.y * 64;
    const float* Ab = A + (size_t)b * NX_ * D_;

    // fill indices (fixed per thread)
    int fr0 = tid >> 3,          fc0 = tid & 7;          // l=0: rows 0..31
    int fr1 = (tid + 256) >> 3,  fc1 = tid & 7;          // l=1: rows 32..63

    float acc[4][4] = {};
    float4 pw0, pw1, pa0, pa1;

    // prologue: prefetch chunk 0
    {
        const int k0 = 0;
        pw0 = *reinterpret_cast<const float4*>(&W [(size_t)(h0 + fr0) * K + k0 + fc0 * 4]);
        pw1 = *reinterpret_cast<const float4*>(&W [(size_t)(h0 + fr1) * K + k0 + fc1 * 4]);
        pa0 = *reinterpret_cast<const float4*>(&Ab[(size_t)(x0 + fr0) * K + k0 + fc0 * 4]);
        pa1 = *reinterpret_cast<const float4*>(&Ab[(size_t)(x0 + fr1) * K + k0 + fc1 * 4]);
    }

    for (int k0 = 0; k0 < K; k0 += 32) {
        // commit prefetched chunk to smem (scatter-transpose)
        Ws[fc0 * 4 + 0][fr0] = pw0.x; Ws[fc0 * 4 + 1][fr0] = pw0.y;
        Ws[fc0 * 4 + 2][fr0] = pw0.z; Ws[fc0 * 4 + 3][fr0] = pw0.w;
        Ws[fc1 * 4 + 0][fr1] = pw1.x; Ws[fc1 * 4 + 1][fr1] = pw1.y;
        Ws[fc1 * 4 + 2][fr1] = pw1.z; Ws[fc1 * 4 + 3][fr1] = pw1.w;
        As[fc0 * 4 + 0][fr0] = pa0.x; As[fc0 * 4 + 1][fr0] = pa0.y;
        As[fc0 * 4 + 2][fr0] = pa0.z; As[fc0 * 4 + 3][fr0] = pa0.w;
        As[fc1 * 4 + 0][fr1] = pa1.x; As[fc1 * 4 + 1][fr1] = pa1.y;
        As[fc1 * 4 + 2][fr1] = pa1.z; As[fc1 * 4 + 3][fr1] = pa1.w;
        __syncthreads();

        // issue next chunk's LDGs early (overlap with FFMA block)
        int kn = k0 + 32;
        if (kn < K) {
            pw0 = *reinterpret_cast<const float4*>(&W [(size_t)(h0 + fr0) * K + kn + fc0 * 4]);
            pw1 = *reinterpret_cast<const float4*>(&W [(size_t)(h0 + fr1) * K + kn + fc1 * 4]);
            pa0 = *reinterpret_cast<const float4*>(&Ab[(size_t)(x0 + fr0) * K + kn + fc0 * 4]);
            pa1 = *reinterpret_cast<const float4*>(&Ab[(size_t)(x0 + fr1) * K + kn + fc1 * 4]);
        }

#pragma unroll
        for (int k = 0; k < 32; k++) {
            float4 a4 = *reinterpret_cast<const float4*>(&Ws[k][ty * 4]);
            float4 b4 = *reinterpret_cast<const float4*>(&As[k][tx * 4]);
            float a[4] = {a4.x, a4.y, a4.z, a4.w};
            float bb[4] = {b4.x, b4.y, b4.z, b4.w};
#pragma unroll
            for (int i = 0; i < 4; i++)
#pragma unroll
                for (int j = 0; j < 4; j++)
                    acc[i][j] += a[i] * bb[j];
        }
        __syncthreads();
    }

#pragma unroll
    for (int i = 0; i < 4; i++) {
        int h = h0 + ty * 4 + i;
        float bb = bias[h];
        __half2 p0 = __floats2half2_rn(acc[i][0] + bb, acc[i][1] + bb);
        __half2 p1 = __floats2half2_rn(acc[i][2] + bb, acc[i][3] + bb);
        uint2 pk = {*reinterpret_cast<unsigned*>(&p0), *reinterpret_cast<unsigned*>(&p1)};
        *reinterpret_cast<uint2*>(&C[((size_t)b * H_ + h) * NX_ + x0 + tx * 4]) = pk;
    }
}

// ---------------------------------------------------------------------------
// Phase 2: S[b][r][x] = sum_h v[h]*tanh(hX[b][h][x] + hR[b][h][r])
// Persistent 296 CTAs, dynamic tile counter. sR2 pre-broadcast (r,r) pairs.
// MUFU double-pumped f16x2 tanh -> at confirmed MUFU floor (~84% util).
// ---------------------------------------------------------------------------
#define NTILES      512
#define SCORE_CTAS  296

__global__ __launch_bounds__(256) void score_kernel(const float* __restrict__ vw) {
    __shared__ __half   sX [32][64];
    __shared__ __half2  sR2[32][64];
    __shared__ __half2  sv2[H_];
    __shared__ unsigned s_tile;

    int tid = threadIdx.x;
    int tx = tid & 15, ty = tid >> 4;
    int frow = tid >> 3, fseg = tid & 7;

    sv2[tid] = __half2half2(__float2half_rn(vw[tid]));

    for (;;) {
        __syncthreads();
        if (tid == 0) s_tile = atomicAdd(&g_tile, 1u);
        __syncthreads();
        unsigned t = s_tile;
        if (t >= NTILES) break;
        int b  = (int)(t >> 6);
        int r0 = (int)((t >> 3) & 7) * 64;
        int x0 = (int)(t & 7) * 64;
        const __half* hXb = g_hXT + (size_t)b * H_ * NX_;
        const __half* hRb = g_hRT + (size_t)b * H_ * NR_;

        float acc[4][4] = {};

        for (int h0 = 0; h0 < H_; h0 += 32) {
            *reinterpret_cast<uint4*>(&sX[frow][fseg * 8]) =
                *reinterpret_cast<const uint4*>(&hXb[(size_t)(h0 + frow) * NX_ + x0 + fseg * 8]);
            uint4 rv = *reinterpret_cast<const uint4*>(&hRb[(size_t)(h0 + frow) * NR_ + r0 + fseg * 8]);
            const __half* rh = reinterpret_cast<const __half*>(&rv);
            __half2* dst = &sR2[frow][fseg * 8];
#pragma unroll
            for (int k = 0; k < 8; k++) dst[k] = __half2half2(rh[k]);
            __syncthreads();

#pragma unroll
            for (int hh = 0; hh < 32; hh += 8) {
                __half2 a2[4][2] = {};
#pragma unroll
                for (int h = 0; h < 8; h++) {
                    int hc = hh + h;
                    __half2 v2 = sv2[h0 + hc];
                    uint2 xu = *reinterpret_cast<const uint2*>(&sX[hc][tx * 4]);
                    uint4 ru = *reinterpret_cast<const uint4*>(&sR2[hc][ty * 4]);
                    __half2 x2[2] = {*reinterpret_cast<__half2*>(&xu.x),
                                     *reinterpret_cast<__half2*>(&xu.y)};
                    __half2 r2[4] = {*reinterpret_cast<__half2*>(&ru.x),
                                     *reinterpret_cast<__half2*>(&ru.y),
                                     *reinterpret_cast<__half2*>(&ru.z),
                                     *reinterpret_cast<__half2*>(&ru.w)};
#pragma unroll
                    for (int i = 0; i < 4; i++)
#pragma unroll
                        for (int j2 = 0; j2 < 2; j2++)
                            a2[i][j2] = __hfma2(v2, tanh2(__hadd2(r2[i], x2[j2])), a2[i][j2]);
                }
#pragma unroll
                for (int i = 0; i < 4; i++)
#pragma unroll
                    for (int j2 = 0; j2 < 2; j2++) {
                        float2 f = __half22float2(a2[i][j2]);
                        acc[i][2 * j2 + 0] += f.x;
                        acc[i][2 * j2 + 1] += f.y;
                    }
            }
            __syncthreads();
        }

        float* Sb = g_S + (size_t)b * NR_ * NX_;
#pragma unroll
        for (int i = 0; i < 4; i++) {
            float4 o = {acc[i][0], acc[i][1], acc[i][2], acc[i][3]};
            *reinterpret_cast<float4*>(&Sb[(size_t)(r0 + ty * 4 + i) * NX_ + x0 + tx * 4]) = o;
        }
    }
}

// ---------------------------------------------------------------------------
// Phase 3: row-wise softmax over 512 x-values of each S[b][r][:] (in place)
// ---------------------------------------------------------------------------
__global__ __launch_bounds__(128) void softmax512_kernel() {
    int row = blockIdx.x;
    float* p = g_S + (size_t)row * NX_;
    int t = threadIdx.x;
    int w = t >> 5, lane = t & 31;

    float4 v = *reinterpret_cast<float4*>(&p[t * 4]);

    float m = fmaxf(fmaxf(v.x, v.y), fmaxf(v.z, v.w));
#pragma unroll
    for (int o = 16; o > 0; o >>= 1) m = fmaxf(m, __shfl_xor_sync(0xffffffffu, m, o));
    __shared__ float sm[4];
    if (lane == 0) sm[w] = m;
    __syncthreads();
    m = fmaxf(fmaxf(sm[0], sm[1]), fmaxf(sm[2], sm[3]));

    v.x = __expf(v.x - m); v.y = __expf(v.y - m);
    v.z = __expf(v.z - m); v.w = __expf(v.w - m);
    float s = v.x + v.y + v.z + v.w;
#pragma unroll
    for (int o = 16; o > 0; o >>= 1) s += __shfl_xor_sync(0xffffffffu, s, o);
    __shared__ float ss[4];
    if (lane == 0) ss[w] = s;
    __syncthreads();
    s = ss[0] + ss[1] + ss[2] + ss[3];

    float inv = 1.0f / s;
    v.x *= inv; v.y *= inv; v.z *= inv; v.w *= inv;
    *reinterpret_cast<float4*>(&p[t * 4]) = v;
}

// ---------------------------------------------------------------------------
// Phase 4: out[b][r][d] = sum_x attn[b][r][x] * X[b][x][d]   (fp32 NN GEMM)
// Register-prefetch double buffering as in proj.
// ---------------------------------------------------------------------------
__global__ __launch_bounds__(256) void out_gemm_kernel(const float* __restrict__ X,
                                                       float* __restrict__ out) {
    __shared__ float As[32][64];   // [k][m=r]
    __shared__ float Bs[32][64];   // [k][n=d]
    int tid = threadIdx.x;
    int tx = tid & 15, ty = tid >> 4;
    int n0 = blockIdx.x * 64, m0 = blockIdx.y * 64, b = blockIdx.z;
    const float* Ab = g_S + (size_t)b * NR_ * NX_;
    const float* Xb = X + (size_t)b * NX_ * D_;

    // fill indices
    int ar0 = tid >> 3,         ac0 = tid & 7;    // A rows 0..31
    int ar1 = (tid + 256) >> 3, ac1 = tid & 7;    // A rows 32..63
    int br0 = tid >> 4,         bc0 = tid & 15;   // B rows 0..15
    int br1 = (tid + 256) >> 4, bc1 = tid & 15;   // B rows 16..31

    float acc[4][4] = {};
    float4 pa0, pa1, pb0, pb1;

    {
        const int k0 = 0;
        pa0 = *reinterpret_cast<const float4*>(&Ab[(size_t)(m0 + ar0) * NX_ + k0 + ac0 * 4]);
        pa1 = *reinterpret_cast<const float4*>(&Ab[(size_t)(m0 + ar1) * NX_ + k0 + ac1 * 4]);
        pb0 = *reinterpret_cast<const float4*>(&Xb[(size_t)(k0 + br0) * D_ + n0 + bc0 * 4]);
        pb1 = *reinterpret_cast<const float4*>(&Xb[(size_t)(k0 + br1) * D_ + n0 + bc1 * 4]);
    }

    for (int k0 = 0; k0 < NX_; k0 += 32) {
        As[ac0 * 4 + 0][ar0] = pa0.x; As[ac0 * 4 + 1][ar0] = pa0.y;
        As[ac0 * 4 + 2][ar0] = pa0.z; As[ac0 * 4 + 3][ar0] = pa0.w;
        As[ac1 * 4 + 0][ar1] = pa1.x; As[ac1 * 4 + 1][ar1] = pa1.y;
        As[ac1 * 4 + 2][ar1] = pa1.z; As[ac1 * 4 + 3][ar1] = pa1.w;
        *reinterpret_cast<float4*>(&Bs[br0][bc0 * 4]) = pb0;
        *reinterpret_cast<float4*>(&Bs[br1][bc1 * 4]) = pb1;
        __syncthreads();

        int kn = k0 + 32;
        if (kn < NX_) {
            pa0 = *reinterpret_cast<const float4*>(&Ab[(size_t)(m0 + ar0) * NX_ + kn + ac0 * 4]);
            pa1 = *reinterpret_cast<const float4*>(&Ab[(size_t)(m0 + ar1) * NX_ + kn + ac1 * 4]);
            pb0 = *reinterpret_cast<const float4*>(&Xb[(size_t)(kn + br0) * D_ + n0 + bc0 * 4]);
            pb1 = *reinterpret_cast<const float4*>(&Xb[(size_t)(kn + br1) * D_ + n0 + bc1 * 4]);
        }

#pragma unroll
        for (int k = 0; k < 32; k++) {
            float4 a4 = *reinterpret_cast<const float4*>(&As[k][ty * 4]);
            float4 b4 = *reinterpret_cast<const float4*>(&Bs[k][tx * 4]);
            float a[4] = {a4.x, a4.y, a4.z, a4.w};
            float bb[4] = {b4.x, b4.y, b4.z, b4.w};
#pragma unroll
            for (int i = 0; i < 4; i++)
#pragma unroll
                for (int j = 0; j < 4; j++)
                    acc[i][j] += a[i] * bb[j];
        }
        __syncthreads();
    }

#pragma unroll
    for (int i = 0; i < 4; i++) {
        float4 o = {acc[i][0], acc[i][1], acc[i][2], acc[i][3]};
        *reinterpret_cast<float4*>(&out[((size_t)b * NR_ + m0 + ty * 4 + i) * D_ + n0 + tx * 4]) = o;
    }
}

// ---------------------------------------------------------------------------
// Launch (graph-capturable, allocation-free).
// Inputs: X, ref, W_X, b_X, W_ref, b_ref, v_w, v_b (v_b drops out of softmax).
// ---------------------------------------------------------------------------
extern "C" void kernel_launch(void* const* d_in, const int* in_sizes, int n_in,
                              void* d_out, int out_size) {
    const float* X     = (const float*)d_in[0];
    const float* ref   = (const float*)d_in[1];
    const float* W_X   = (const float*)d_in[2];
    const float* b_X   = (const float*)d_in[3];
    const float* W_ref = (const float*)d_in[4];
    const float* b_ref = (const float*)d_in[5];
    const float* v_w   = (const float*)d_in[6];
    float* out = (float*)d_out;

    dim3 blk(256);
    proj_kernel<<<dim3(NX_ / 64, H_ / 64, 2 * B_), blk>>>(X, ref, W_X, b_X, W_ref, b_ref);
    score_kernel<<<SCORE_CTAS, blk>>>(v_w);
    softmax512_kernel<<<B_ * NR_, 128>>>();
    out_gemm_kernel<<<dim3(D_ / 64, NR_ / 64, B_), blk>>>(X, out);
}

// round 9
// speedup vs baseline: 1.0269x; 1.0269x over previous
#include <cuda_runtime.h>
#include <cuda_fp16.h>

#define B_   8
#define NX_  512
#define NR_  512
#define D_   256
#define H_   256

// Scratch (device globals — no allocation allowed anywhere)
__device__ __half   g_hXT  [B_ * H_ * NX_];   // [b][h][x]  fp16
__device__ __half   g_hRT  [B_ * H_ * NR_];   // [b][h][r]  fp16
__device__ float    g_ST   [B_ * NX_ * NR_];  // [b][x][r]  exp(score), fp32
__device__ __half   g_attnT[B_ * NX_ * NR_];  // [b][x][r]  attn, fp16
__device__ __half   g_Xh   [B_ * NX_ * D_];   // [b][x][d]  X in fp16
__device__ unsigned g_tile;                   // dynamic tile counter for score

__device__ __forceinline__ __half2 tanh2(__half2 x) {
    __half2 y;
    asm("tanh.approx.f16x2 %0, %1;"
        : "=r"(*reinterpret_cast<unsigned*>(&y))
        : "r"(*reinterpret_cast<unsigned*>(&x)));
    return y;
}

__device__ __forceinline__ unsigned smem_u32(const void* p) {
    return (unsigned)__cvta_generic_to_shared(p);
}
#define CP16(dst, src) asm volatile("cp.async.cg.shared.global [%0], [%1], 16;" :: "r"(dst), "l"(src))
#define CP_COMMIT()    asm volatile("cp.async.commit_group;")
#define CP_WAIT0()     asm volatile("cp.async.wait_group 0;" ::: "memory")

// ---------------------------------------------------------------------------
// Phase 0: Xh[b][x][d] = fp16(X)   (one-time convert for the output GEMM)
// ---------------------------------------------------------------------------
__global__ __launch_bounds__(256) void xh_kernel(const float* __restrict__ X) {
    int idx = blockIdx.x * 256 + threadIdx.x;           // 262144 threads, 4 elems each
    float4 v = reinterpret_cast<const float4*>(X)[idx];
    __half2 h0 = __floats2half2_rn(v.x, v.y);
    __half2 h1 = __floats2half2_rn(v.z, v.w);
    uint2 pk = {*reinterpret_cast<unsigned*>(&h0), *reinterpret_cast<unsigned*>(&h1)};
    reinterpret_cast<uint2*>(g_Xh)[idx] = pk;
}

// ---------------------------------------------------------------------------
// Phase 1 (merged): hT[b][h][x] = sum_d W[h][d]*A[b][x][d] + bias[h], fp16 out.
// grid.z in [0,16): z<8 -> X -> g_hXT ; z>=8 -> ref -> g_hRT. (R7 form)
// ---------------------------------------------------------------------------
__global__ __launch_bounds__(256) void proj_kernel(const float* __restrict__ X,
                                                   const float* __restrict__ ref,
                                                   const float* __restrict__ W_X,
                                                   const float* __restrict__ b_X,
                                                   const float* __restrict__ W_ref,
                                                   const float* __restrict__ b_ref) {
    __shared__ float Ws[32][64];   // [k][h]
    __shared__ float As[32][64];   // [k][x]
    int tid = threadIdx.x;
    if (blockIdx.x == 0 && blockIdx.y == 0 && blockIdx.z == 0 && tid == 0)
        g_tile = 0u;

    int z = blockIdx.z;
    int b = z & 7;
    const float* A    = (z < 8) ? X     : ref;
    const float* W    = (z < 8) ? W_X   : W_ref;
    const float* bias = (z < 8) ? b_X   : b_ref;
    __half*      C    = (z < 8) ? g_hXT : g_hRT;

    const int K = D_;
    int tx = tid & 15, ty = tid >> 4;
    int x0 = blockIdx.x * 64, h0 = blockIdx.y * 64;
    const float* Ab = A + (size_t)b * NX_ * D_;

    float acc[4][4] = {};

    for (int k0 = 0; k0 < K; k0 += 32) {
#pragma unroll
        for (int l = 0; l < 2; l++) {
            int f = tid + l * 256;
            int row = f >> 3, c4 = f & 7;
            float4 w = *reinterpret_cast<const float4*>(&W[(size_t)(h0 + row) * K + k0 + c4 * 4]);
            Ws[c4 * 4 + 0][row] = w.x; Ws[c4 * 4 + 1][row] = w.y;
            Ws[c4 * 4 + 2][row] = w.z; Ws[c4 * 4 + 3][row] = w.w;
            float4 v = *reinterpret_cast<const float4*>(&Ab[(size_t)(x0 + row) * K + k0 + c4 * 4]);
            As[c4 * 4 + 0][row] = v.x; As[c4 * 4 + 1][row] = v.y;
            As[c4 * 4 + 2][row] = v.z; As[c4 * 4 + 3][row] = v.w;
        }
        __syncthreads();
#pragma unroll
        for (int k = 0; k < 32; k++) {
            float4 a4 = *reinterpret_cast<const float4*>(&Ws[k][ty * 4]);
            float4 b4 = *reinterpret_cast<const float4*>(&As[k][tx * 4]);
            float a[4] = {a4.x, a4.y, a4.z, a4.w};
            float bb[4] = {b4.x, b4.y, b4.z, b4.w};
#pragma unroll
            for (int i = 0; i < 4; i++)
#pragma unroll
                for (int j = 0; j < 4; j++)
                    acc[i][j] += a[i] * bb[j];
        }
        __syncthreads();
    }

#pragma unroll
    for (int i = 0; i < 4; i++) {
        int h = h0 + ty * 4 + i;
        float bb = bias[h];
        __half2 p0 = __floats2half2_rn(acc[i][0] + bb, acc[i][1] + bb);
        __half2 p1 = __floats2half2_rn(acc[i][2] + bb, acc[i][3] + bb);
        uint2 pk = {*reinterpret_cast<unsigned*>(&p0), *reinterpret_cast<unsigned*>(&p1)};
        *reinterpret_cast<uint2*>(&C[((size_t)b * H_ + h) * NX_ + x0 + tx * 4]) = pk;
    }
}

// ---------------------------------------------------------------------------
// Phase 2: S_T[b][x][r] = exp( sum_h v[h]*tanh(hX[b][h][x] + hR[b][h][r]) )
// Persistent 296 CTAs, dynamic tile counter. Roles swapped vs R7 (ty->x,
// tx->r) so the TRANSPOSED store is coalesced. sX2 pre-broadcast (x,x) pairs.
// exp fused here (scores bounded |S|<~13 -> max-free softmax is fp32-safe).
// Arithmetic per score element identical to R7 -> score numerics unchanged.
// ---------------------------------------------------------------------------
#define NTILES      512
#define SCORE_CTAS  296

__global__ __launch_bounds__(256) void score_kernel(const float* __restrict__ vw) {
    __shared__ __half2  sX2[32][64];    // [h][x] as (x,x)   8 KB
    __shared__ __half   sR [32][64];    // [h][r]            4 KB
    __shared__ __half2  sv2[H_];
    __shared__ unsigned s_tile;

    int tid = threadIdx.x;
    int tx = tid & 15, ty = tid >> 4;
    int frow = tid >> 3, fseg = tid & 7;

    sv2[tid] = __half2half2(__float2half_rn(vw[tid]));

    for (;;) {
        __syncthreads();
        if (tid == 0) s_tile = atomicAdd(&g_tile, 1u);
        __syncthreads();
        unsigned t = s_tile;
        if (t >= NTILES) break;
        int b  = (int)(t >> 6);
        int r0 = (int)((t >> 3) & 7) * 64;
        int x0 = (int)(t & 7) * 64;
        const __half* hXb = g_hXT + (size_t)b * H_ * NX_;
        const __half* hRb = g_hRT + (size_t)b * H_ * NR_;

        float acc[4][4] = {};   // [i: x][j: r]

        for (int h0 = 0; h0 < H_; h0 += 32) {
            // X side: expand to (x,x) pairs; R side: plain copy
            uint4 xv = *reinterpret_cast<const uint4*>(&hXb[(size_t)(h0 + frow) * NX_ + x0 + fseg * 8]);
            const __half* xh = reinterpret_cast<const __half*>(&xv);
            __half2* dst = &sX2[frow][fseg * 8];
#pragma unroll
            for (int k = 0; k < 8; k++) dst[k] = __half2half2(xh[k]);
            *reinterpret_cast<uint4*>(&sR[frow][fseg * 8]) =
                *reinterpret_cast<const uint4*>(&hRb[(size_t)(h0 + frow) * NR_ + r0 + fseg * 8]);
            __syncthreads();

#pragma unroll
            for (int hh = 0; hh < 32; hh += 8) {
                __half2 a2[4][2] = {};
#pragma unroll
                for (int h = 0; h < 8; h++) {
                    int hc = hh + h;
                    __half2 v2 = sv2[h0 + hc];
                    uint4 xu = *reinterpret_cast<const uint4*>(&sX2[hc][ty * 4]);
                    uint2 ru = *reinterpret_cast<const uint2*>(&sR [hc][tx * 4]);
                    __half2 x2[4] = {*reinterpret_cast<__half2*>(&xu.x),
                                     *reinterpret_cast<__half2*>(&xu.y),
                                     *reinterpret_cast<__half2*>(&xu.z),
                                     *reinterpret_cast<__half2*>(&xu.w)};
                    __half2 r2[2] = {*reinterpret_cast<__half2*>(&ru.x),
                                     *reinterpret_cast<__half2*>(&ru.y)};
#pragma unroll
                    for (int i = 0; i < 4; i++)
#pragma unroll
                        for (int j2 = 0; j2 < 2; j2++)
                            a2[i][j2] = __hfma2(v2, tanh2(__hadd2(x2[i], r2[j2])), a2[i][j2]);
                }
#pragma unroll
                for (int i = 0; i < 4; i++)
#pragma unroll
                    for (int j2 = 0; j2 < 2; j2++) {
                        float2 f = __half22float2(a2[i][j2]);
                        acc[i][2 * j2 + 0] += f.x;
                        acc[i][2 * j2 + 1] += f.y;
                    }
            }
            __syncthreads();
        }

        // store exp(score), transposed: row = x, cols = r (coalesced)
        float* Sb = g_ST + (size_t)b * NX_ * NR_;
#pragma unroll
        for (int i = 0; i < 4; i++) {
            float4 o = {__expf(acc[i][0]), __expf(acc[i][1]),
                        __expf(acc[i][2]), __expf(acc[i][3])};
            *reinterpret_cast<float4*>(&Sb[(size_t)(x0 + ty * 4 + i) * NR_ + r0 + tx * 4]) = o;
        }
    }
}

// ---------------------------------------------------------------------------
// Phase 3: column softmax finalize. S_T already holds exp(score).
// attn_T[b][x][r] = S_T[b][x][r] / sum_x S_T[b][x][r],  fp16 out.
// Block: 128 thr = 32 r-columns x 4 x-segments. Grid (NR/32, B) = 128 blocks.
// ---------------------------------------------------------------------------
__global__ __launch_bounds__(128) void softmaxT_kernel() {
    int t = threadIdx.x;
    int rx = t & 31, seg = t >> 5;
    int r = blockIdx.x * 32 + rx, b = blockIdx.y;
    const float* base = g_ST + (size_t)b * NX_ * NR_ + r;

    float s = 0.0f;
#pragma unroll 8
    for (int x = seg * 128; x < seg * 128 + 128; x++)
        s += base[(size_t)x * NR_];

    __shared__ float ssum[4][32];
    __shared__ float sinv[32];
    ssum[seg][rx] = s;
    __syncthreads();
    if (t < 32) sinv[t] = 1.0f / (ssum[0][t] + ssum[1][t] + ssum[2][t] + ssum[3][t]);
    __syncthreads();
    float inv = sinv[rx];

    __half* ob = g_attnT + (size_t)b * NX_ * NR_ + r;
#pragma unroll 8
    for (int x = seg * 128; x < seg * 128 + 128; x++)
        ob[(size_t)x * NR_] = __float2half_rn(base[(size_t)x * NR_] * inv);
}

// ---------------------------------------------------------------------------
// Phase 4: out[b][r][d] = sum_x attn_T[b][x][r] * Xh[b][x][d]
// Both operands k-major fp16 -> cp.async double-buffered pipeline, HFMA2
// compute (4r x 4d per thread), fp16 chunk-accumulate flushed to fp32 every 8k.
// ---------------------------------------------------------------------------
__global__ __launch_bounds__(256) void out_gemm_kernel(float* __restrict__ out) {
    __shared__ __half sA[2][32][64];   // attn_T [k=x][m=r]  4 KB/buf
    __shared__ __half sB[2][32][64];   // Xh     [k=x][n=d]  4 KB/buf
    int tid = threadIdx.x;
    int tx = tid & 15, ty = tid >> 4;
    int n0 = blockIdx.x * 64, m0 = blockIdx.y * 64, b = blockIdx.z;
    const __half* Ab = g_attnT + (size_t)b * NX_ * NR_;
    const __half* Bb = g_Xh    + (size_t)b * NX_ * D_;
    int frow = tid >> 3, fseg = tid & 7;

    unsigned dA0 = smem_u32(&sA[0][frow][fseg * 8]);
    unsigned dB0 = smem_u32(&sB[0][frow][fseg * 8]);
    unsigned dA1 = smem_u32(&sA[1][frow][fseg * 8]);
    unsigned dB1 = smem_u32(&sB[1][frow][fseg * 8]);

    float acc[4][4] = {};

    // prologue: chunk 0 -> buf 0
    CP16(dA0, &Ab[(size_t)frow * NR_ + m0 + fseg * 8]);
    CP16(dB0, &Bb[(size_t)frow * D_  + n0 + fseg * 8]);
    CP_COMMIT();

    for (int it = 0; it < 16; it++) {
        CP_WAIT0();
        __syncthreads();   // data visible to all; all threads done with other buf
        if (it < 15) {
            int kk = (it + 1) * 32;
            unsigned dA = (it & 1) ? dA0 : dA1;
            unsigned dB = (it & 1) ? dB0 : dB1;
            CP16(dA, &Ab[(size_t)(kk + frow) * NR_ + m0 + fseg * 8]);
            CP16(dB, &Bb[(size_t)(kk + frow) * D_  + n0 + fseg * 8]);
            CP_COMMIT();
        }
        int buf = it & 1;
#pragma unroll
        for (int k8 = 0; k8 < 32; k8 += 8) {
            __half2 acc2[4][2] = {};
#pragma unroll
            for (int k = 0; k < 8; k++) {
                int kk = k8 + k;
                uint2 au = *reinterpret_cast<const uint2*>(&sA[buf][kk][ty * 4]);
                uint2 bu = *reinterpret_cast<const uint2*>(&sB[buf][kk][tx * 4]);
                const __half* ah = reinterpret_cast<const __half*>(&au);
                __half2 b2[2] = {*reinterpret_cast<__half2*>(&bu.x),
                                 *reinterpret_cast<__half2*>(&bu.y)};
#pragma unroll
                for (int i = 0; i < 4; i++) {
                    __half2 ai = __half2half2(ah[i]);
#pragma unroll
                    for (int j2 = 0; j2 < 2; j2++)
                        acc2[i][j2] = __hfma2(ai, b2[j2], acc2[i][j2]);
                }
            }
#pragma unroll
            for (int i = 0; i < 4; i++)
#pragma unroll
                for (int j2 = 0; j2 < 2; j2++) {
                    float2 f = __half22float2(acc2[i][j2]);
                    acc[i][2 * j2 + 0] += f.x;
                    acc[i][2 * j2 + 1] += f.y;
                }
        }
    }

#pragma unroll
    for (int i = 0; i < 4; i++) {
        float4 o = {acc[i][0], acc[i][1], acc[i][2], acc[i][3]};
        *reinterpret_cast<float4*>(&out[((size_t)b * NR_ + m0 + ty * 4 + i) * D_ + n0 + tx * 4]) = o;
    }
}

// ---------------------------------------------------------------------------
// Launch (graph-capturable, allocation-free).
// Inputs: X, ref, W_X, b_X, W_ref, b_ref, v_w, v_b (v_b drops out of softmax).
// ---------------------------------------------------------------------------
extern "C" void kernel_launch(void* const* d_in, const int* in_sizes, int n_in,
                              void* d_out, int out_size) {
    const float* X     = (const float*)d_in[0];
    const float* ref   = (const float*)d_in[1];
    const float* W_X   = (const float*)d_in[2];
    const float* b_X   = (const float*)d_in[3];
    const float* W_ref = (const float*)d_in[4];
    const float* b_ref = (const float*)d_in[5];
    const float* v_w   = (const float*)d_in[6];
    float* out = (float*)d_out;

    dim3 blk(256);
    xh_kernel<<<(B_ * NX_ * D_ / 4) / 256, blk>>>(X);
    proj_kernel<<<dim3(NX_ / 64, H_ / 64, 2 * B_), blk>>>(X, ref, W_X, b_X, W_ref, b_ref);
    score_kernel<<<SCORE_CTAS, blk>>>(v_w);
    softmaxT_kernel<<<dim3(NR_ / 32, B_), 128>>>();
    out_gemm_kernel<<<dim3(D_ / 64, NR_ / 64, B_), blk>>>(out);
}

// round 12
// speedup vs baseline: 1.1083x; 1.0792x over previous
#include <cuda_runtime.h>
#include <cuda_fp16.h>

#define B_   8
#define NX_  512
#define NR_  512
#define D_   256
#define H_   256

// Scratch (device globals — no allocation allowed anywhere)
__device__ __half   g_hXT  [B_ * H_ * NX_];   // [b][h][x]  fp16
__device__ __half   g_hRT  [B_ * H_ * NR_];   // [b][h][r]  fp16
__device__ float    g_ST   [B_ * NX_ * NR_];  // [b][x][r]  exp(score), fp32
__device__ __half   g_attnT[B_ * NX_ * NR_];  // [b][x][r]  attn, fp16
__device__ __half   g_Xh   [B_ * NX_ * D_];   // [b][x][d]  X fp16 (out_gemm B)
__device__ __half   g_XT   [B_ * D_ * NX_];   // [b][d][x]  X^T fp16 (proj B)
__device__ __half   g_refT [B_ * D_ * NR_];   // [b][d][r]  ref^T fp16
__device__ __half   g_WXT  [D_ * H_];         // [d][h]     W_X^T fp16 (proj A)
__device__ __half   g_WRT  [D_ * H_];         // [d][h]     W_ref^T fp16
__device__ float    g_part [8][B_ * NR_];     // partial column sums
__device__ float    g_inv  [B_ * NR_];        // 1/colsum
__device__ unsigned g_tile;                   // dynamic tile counter for score

__device__ __forceinline__ __half2 tanh2(__half2 x) {
    __half2 y;
    asm("tanh.approx.f16x2 %0, %1;"
        : "=r"(*reinterpret_cast<unsigned*>(&y))
        : "r"(*reinterpret_cast<unsigned*>(&x)));
    return y;
}
__device__ __forceinline__ unsigned smem_u32(const void* p) {
    return (unsigned)__cvta_generic_to_shared(p);
}
#define CP16(dst, src) asm volatile("cp.async.cg.shared.global [%0], [%1], 16;" :: "r"(dst), "l"(src))
#define CP_COMMIT()    asm volatile("cp.async.commit_group;")
#define CP_WAIT0()     asm volatile("cp.async.wait_group 0;" ::: "memory")

// ---------------------------------------------------------------------------
// Prep A: Xh = fp16(X) (row layout, for out_gemm); also resets tile counter.
// ---------------------------------------------------------------------------
__global__ __launch_bounds__(256) void xh_kernel(const float* __restrict__ X) {
    if (blockIdx.x == 0 && threadIdx.x == 0) g_tile = 0u;
    int idx = blockIdx.x * 256 + threadIdx.x;   // 1024 blocks -> 262144 float4
    float4 v = reinterpret_cast<const float4*>(X)[idx];
    __half2 h0 = __floats2half2_rn(v.x, v.y);
    __half2 h1 = __floats2half2_rn(v.z, v.w);
    uint2 pk = {*reinterpret_cast<unsigned*>(&h0), *reinterpret_cast<unsigned*>(&h1)};
    reinterpret_cast<uint2*>(g_Xh)[idx] = pk;
}

// ---------------------------------------------------------------------------
// Prep B: transpose activations to fp16 [d][x]: z<8 -> X -> g_XT, else ref.
// Block (32,8), 32x32 tiles, smem pad 33.
// ---------------------------------------------------------------------------
__global__ __launch_bounds__(256) void transA_kernel(const float* __restrict__ X,
                                                     const float* __restrict__ ref) {
    __shared__ float s[32][33];
    int z = blockIdx.z, b = z & 7;
    const float* in = ((z < 8) ? X : ref) + (size_t)b * NX_ * D_;
    __half* out = ((z < 8) ? g_XT : g_refT) + (size_t)b * D_ * NX_;
    int x0 = blockIdx.x * 32, d0 = blockIdx.y * 32;
    int tx = threadIdx.x, ty = threadIdx.y;
#pragma unroll
    for (int l = 0; l < 4; l++)
        s[ty + l * 8][tx] = in[(size_t)(x0 + ty + l * 8) * D_ + d0 + tx];
    __syncthreads();
#pragma unroll
    for (int l = 0; l < 4; l++)
        out[(size_t)(d0 + ty + l * 8) * NX_ + x0 + tx] = __float2half_rn(s[tx][ty + l * 8]);
}

// ---------------------------------------------------------------------------
// Prep C: transpose weights to fp16 [d][h]: z=0 -> W_X, z=1 -> W_ref.
// ---------------------------------------------------------------------------
__global__ __launch_bounds__(256) void transW_kernel(const float* __restrict__ W_X,
                                                     const float* __restrict__ W_ref) {
    __shared__ float s[32][33];
    int z = blockIdx.z;
    const float* in = (z == 0) ? W_X : W_ref;
    __half* out = (z == 0) ? g_WXT : g_WRT;
    int h0 = blockIdx.x * 32, d0 = blockIdx.y * 32;
    int tx = threadIdx.x, ty = threadIdx.y;
#pragma unroll
    for (int l = 0; l < 4; l++)
        s[ty + l * 8][tx] = in[(size_t)(h0 + ty + l * 8) * D_ + d0 + tx];
    __syncthreads();
#pragma unroll
    for (int l = 0; l < 4; l++)
        out[(size_t)(d0 + ty + l * 8) * H_ + h0 + tx] = __float2half_rn(s[tx][ty + l * 8]);
}

// ---------------------------------------------------------------------------
// Phase 1: hT[b][h][x] = sum_d WT[d][h]*XT[b][d][x] + bias[h], fp16 out.
// Same cp.async + HFMA2 engine as out_gemm (k-major operands, no transpose).
// grid (NX/64, H/64, 16): z<8 -> X side, z>=8 -> ref side.
// ---------------------------------------------------------------------------
__global__ __launch_bounds__(256) void proj16_kernel(const float* __restrict__ b_X,
                                                     const float* __restrict__ b_ref) {
    __shared__ __half sA[2][32][64];   // WT tile  [k=d][m=h]
    __shared__ __half sB[2][32][64];   // XT tile  [k=d][n=x]
    int tid = threadIdx.x;
    int tx = tid & 15, ty = tid >> 4;
    int z = blockIdx.z, b = z & 7;
    const __half* WT = (z < 8) ? g_WXT : g_WRT;
    const __half* XT = ((z < 8) ? g_XT : g_refT) + (size_t)b * D_ * NX_;
    const float* bias = (z < 8) ? b_X : b_ref;
    __half* C = ((z < 8) ? g_hXT : g_hRT) + (size_t)b * H_ * NX_;
    int n0 = blockIdx.x * 64, m0 = blockIdx.y * 64;
    int frow = tid >> 3, fseg = tid & 7;

    unsigned dA0 = smem_u32(&sA[0][frow][fseg * 8]);
    unsigned dB0 = smem_u32(&sB[0][frow][fseg * 8]);
    unsigned dA1 = smem_u32(&sA[1][frow][fseg * 8]);
    unsigned dB1 = smem_u32(&sB[1][frow][fseg * 8]);

    float acc[4][4] = {};

    CP16(dA0, &WT[(size_t)frow * H_  + m0 + fseg * 8]);
    CP16(dB0, &XT[(size_t)frow * NX_ + n0 + fseg * 8]);
    CP_COMMIT();

    for (int it = 0; it < 8; it++) {            // K = 256
        CP_WAIT0();
        __syncthreads();
        if (it < 7) {
            int kk = (it + 1) * 32;
            unsigned dA = (it & 1) ? dA0 : dA1;
            unsigned dB = (it & 1) ? dB0 : dB1;
            CP16(dA, &WT[(size_t)(kk + frow) * H_  + m0 + fseg * 8]);
            CP16(dB, &XT[(size_t)(kk + frow) * NX_ + n0 + fseg * 8]);
            CP_COMMIT();
        }
        int buf = it & 1;
#pragma unroll
        for (int k8 = 0; k8 < 32; k8 += 8) {
            __half2 acc2[4][2] = {};
#pragma unroll
            for (int k = 0; k < 8; k++) {
                int kk = k8 + k;
                uint2 au = *reinterpret_cast<const uint2*>(&sA[buf][kk][ty * 4]);
                uint2 bu = *reinterpret_cast<const uint2*>(&sB[buf][kk][tx * 4]);
                const __half* ah = reinterpret_cast<const __half*>(&au);
                __half2 b2[2] = {*reinterpret_cast<__half2*>(&bu.x),
                                 *reinterpret_cast<__half2*>(&bu.y)};
#pragma unroll
                for (int i = 0; i < 4; i++) {
                    __half2 ai = __half2half2(ah[i]);
#pragma unroll
                    for (int j2 = 0; j2 < 2; j2++)
                        acc2[i][j2] = __hfma2(ai, b2[j2], acc2[i][j2]);
                }
            }
#pragma unroll
            for (int i = 0; i < 4; i++)
#pragma unroll
                for (int j2 = 0; j2 < 2; j2++) {
                    float2 f = __half22float2(acc2[i][j2]);
                    acc[i][2 * j2 + 0] += f.x;
                    acc[i][2 * j2 + 1] += f.y;
                }
        }
    }

#pragma unroll
    for (int i = 0; i < 4; i++) {
        int h = m0 + ty * 4 + i;
        float bb = bias[h];
        __half2 p0 = __floats2half2_rn(acc[i][0] + bb, acc[i][1] + bb);
        __half2 p1 = __floats2half2_rn(acc[i][2] + bb, acc[i][3] + bb);
        uint2 pk = {*reinterpret_cast<unsigned*>(&p0), *reinterpret_cast<unsigned*>(&p1)};
        *reinterpret_cast<uint2*>(&C[(size_t)h * NX_ + n0 + tx * 4]) = pk;
    }
}

// ---------------------------------------------------------------------------
// Phase 2: S_T[b][x][r] = exp( sum_h v[h]*tanh(hX[b][h][x] + hR[b][h][r]) )
// Persistent 296 CTAs, dynamic tile counter. At confirmed MUFU floor.
// ---------------------------------------------------------------------------
#define NTILES      512
#define SCORE_CTAS  296

__global__ __launch_bounds__(256) void score_kernel(const float* __restrict__ vw) {
    __shared__ __half2  sX2[32][64];
    __shared__ __half   sR [32][64];
    __shared__ __half2  sv2[H_];
    __shared__ unsigned s_tile;

    int tid = threadIdx.x;
    int tx = tid & 15, ty = tid >> 4;
    int frow = tid >> 3, fseg = tid & 7;

    sv2[tid] = __half2half2(__float2half_rn(vw[tid]));

    for (;;) {
        __syncthreads();
        if (tid == 0) s_tile = atomicAdd(&g_tile, 1u);
        __syncthreads();
        unsigned t = s_tile;
        if (t >= NTILES) break;
        int b  = (int)(t >> 6);
        int r0 = (int)((t >> 3) & 7) * 64;
        int x0 = (int)(t & 7) * 64;
        const __half* hXb = g_hXT + (size_t)b * H_ * NX_;
        const __half* hRb = g_hRT + (size_t)b * H_ * NR_;

        float acc[4][4] = {};

        for (int h0 = 0; h0 < H_; h0 += 32) {
            uint4 xv = *reinterpret_cast<const uint4*>(&hXb[(size_t)(h0 + frow) * NX_ + x0 + fseg * 8]);
            const __half* xh = reinterpret_cast<const __half*>(&xv);
            __half2* dst = &sX2[frow][fseg * 8];
#pragma unroll
            for (int k = 0; k < 8; k++) dst[k] = __half2half2(xh[k]);
            *reinterpret_cast<uint4*>(&sR[frow][fseg * 8]) =
                *reinterpret_cast<const uint4*>(&hRb[(size_t)(h0 + frow) * NR_ + r0 + fseg * 8]);
            __syncthreads();

#pragma unroll
            for (int hh = 0; hh < 32; hh += 8) {
                __half2 a2[4][2] = {};
#pragma unroll
                for (int h = 0; h < 8; h++) {
                    int hc = hh + h;
                    __half2 v2 = sv2[h0 + hc];
                    uint4 xu = *reinterpret_cast<const uint4*>(&sX2[hc][ty * 4]);
                    uint2 ru = *reinterpret_cast<const uint2*>(&sR [hc][tx * 4]);
                    __half2 x2[4] = {*reinterpret_cast<__half2*>(&xu.x),
                                     *reinterpret_cast<__half2*>(&xu.y),
                                     *reinterpret_cast<__half2*>(&xu.z),
                                     *reinterpret_cast<__half2*>(&xu.w)};
                    __half2 r2[2] = {*reinterpret_cast<__half2*>(&ru.x),
                                     *reinterpret_cast<__half2*>(&ru.y)};
#pragma unroll
                    for (int i = 0; i < 4; i++)
#pragma unroll
                        for (int j2 = 0; j2 < 2; j2++)
                            a2[i][j2] = __hfma2(v2, tanh2(__hadd2(x2[i], r2[j2])), a2[i][j2]);
                }
#pragma unroll
                for (int i = 0; i < 4; i++)
#pragma unroll
                    for (int j2 = 0; j2 < 2; j2++) {
                        float2 f = __half22float2(a2[i][j2]);
                        acc[i][2 * j2 + 0] += f.x;
                        acc[i][2 * j2 + 1] += f.y;
                    }
            }
            __syncthreads();
        }

        float* Sb = g_ST + (size_t)b * NX_ * NR_;
#pragma unroll
        for (int i = 0; i < 4; i++) {
            float4 o = {__expf(acc[i][0]), __expf(acc[i][1]),
                        __expf(acc[i][2]), __expf(acc[i][3])};
            *reinterpret_cast<float4*>(&Sb[(size_t)(x0 + ty * 4 + i) * NR_ + r0 + tx * 4]) = o;
        }
    }
}

// ---------------------------------------------------------------------------
// Phase 3a: partial column sums over x (deterministic, no atomics).
// grid (8 xseg, NR/256, B), block 256. Coalesced 1KB rows.
// ---------------------------------------------------------------------------
__global__ __launch_bounds__(256) void colsum_kernel() {
    int seg = blockIdx.x, b = blockIdx.z;
    int r = blockIdx.y * 256 + threadIdx.x;
    const float* base = g_ST + (size_t)b * NX_ * NR_ + r;
    float s = 0.0f;
    int x0 = seg * 64;
#pragma unroll 8
    for (int x = x0; x < x0 + 64; x++)
        s += base[(size_t)x * NR_];
    g_part[seg][b * NR_ + r] = s;
}

// Phase 3b: inv[b*NR+r] = 1 / sum of 8 partials.  16 blocks x 256.
__global__ __launch_bounds__(256) void inv_kernel() {
    int i = blockIdx.x * 256 + threadIdx.x;
    float s = 0.0f;
#pragma unroll
    for (int p = 0; p < 8; p++) s += g_part[p][i];
    g_inv[i] = 1.0f / s;
}

// Phase 3c: attn_T = ST * inv (broadcast per r), fp16 out. 2048 blocks x 256.
__global__ __launch_bounds__(256) void norm_kernel() {
    int flat4 = blockIdx.x * 256 + threadIdx.x;     // float4 index
    int idx = flat4 * 4;
    int r = idx & (NR_ - 1);
    int b = idx >> 18;                               // / (NX_*NR_)
    float4 s = reinterpret_cast<const float4*>(g_ST)[flat4];
    float4 iv = *reinterpret_cast<const float4*>(&g_inv[b * NR_ + r]);
    __half2 h0 = __floats2half2_rn(s.x * iv.x, s.y * iv.y);
    __half2 h1 = __floats2half2_rn(s.z * iv.z, s.w * iv.w);
    uint2 pk = {*reinterpret_cast<unsigned*>(&h0), *reinterpret_cast<unsigned*>(&h1)};
    reinterpret_cast<uint2*>(g_attnT)[flat4] = pk;
}

// ---------------------------------------------------------------------------
// Phase 4: out[b][r][d] = sum_x attn_T[b][x][r] * Xh[b][x][d]
// cp.async double-buffered fp16 HFMA2 GEMM (R9-validated).
// ---------------------------------------------------------------------------
__global__ __launch_bounds__(256) void out_gemm_kernel(float* __restrict__ out) {
    __shared__ __half sA[2][32][64];
    __shared__ __half sB[2][32][64];
    int tid = threadIdx.x;
    int tx = tid & 15, ty = tid >> 4;
    int n0 = blockIdx.x * 64, m0 = blockIdx.y * 64, b = blockIdx.z;
    const __half* Ab = g_attnT + (size_t)b * NX_ * NR_;
    const __half* Bb = g_Xh    + (size_t)b * NX_ * D_;
    int frow = tid >> 3, fseg = tid & 7;

    unsigned dA0 = smem_u32(&sA[0][frow][fseg * 8]);
    unsigned dB0 = smem_u32(&sB[0][frow][fseg * 8]);
    unsigned dA1 = smem_u32(&sA[1][frow][fseg * 8]);
    unsigned dB1 = smem_u32(&sB[1][frow][fseg * 8]);

    float acc[4][4] = {};

    CP16(dA0, &Ab[(size_t)frow * NR_ + m0 + fseg * 8]);
    CP16(dB0, &Bb[(size_t)frow * D_  + n0 + fseg * 8]);
    CP_COMMIT();

    for (int it = 0; it < 16; it++) {
        CP_WAIT0();
        __syncthreads();
        if (it < 15) {
            int kk = (it + 1) * 32;
            unsigned dA = (it & 1) ? dA0 : dA1;
            unsigned dB = (it & 1) ? dB0 : dB1;
            CP16(dA, &Ab[(size_t)(kk + frow) * NR_ + m0 + fseg * 8]);
            CP16(dB, &Bb[(size_t)(kk + frow) * D_  + n0 + fseg * 8]);
            CP_COMMIT();
        }
        int buf = it & 1;
#pragma unroll
        for (int k8 = 0; k8 < 32; k8 += 8) {
            __half2 acc2[4][2] = {};
#pragma unroll
            for (int k = 0; k < 8; k++) {
                int kk = k8 + k;
                uint2 au = *reinterpret_cast<const uint2*>(&sA[buf][kk][ty * 4]);
                uint2 bu = *reinterpret_cast<const uint2*>(&sB[buf][kk][tx * 4]);
                const __half* ah = reinterpret_cast<const __half*>(&au);
                __half2 b2[2] = {*reinterpret_cast<__half2*>(&bu.x),
                                 *reinterpret_cast<__half2*>(&bu.y)};
#pragma unroll
                for (int i = 0; i < 4; i++) {
                    __half2 ai = __half2half2(ah[i]);
#pragma unroll
                    for (int j2 = 0; j2 < 2; j2++)
                        acc2[i][j2] = __hfma2(ai, b2[j2], acc2[i][j2]);
                }
            }
#pragma unroll
            for (int i = 0; i < 4; i++)
#pragma unroll
                for (int j2 = 0; j2 < 2; j2++) {
                    float2 f = __half22float2(acc2[i][j2]);
                    acc[i][2 * j2 + 0] += f.x;
                    acc[i][2 * j2 + 1] += f.y;
                }
        }
    }

#pragma unroll
    for (int i = 0; i < 4; i++) {
        float4 o = {acc[i][0], acc[i][1], acc[i][2], acc[i][3]};
        *reinterpret_cast<float4*>(&out[((size_t)b * NR_ + m0 + ty * 4 + i) * D_ + n0 + tx * 4]) = o;
    }
}

// ---------------------------------------------------------------------------
// Launch (graph-capturable, allocation-free).
// Inputs: X, ref, W_X, b_X, W_ref, b_ref, v_w, v_b (v_b drops out of softmax).
// ---------------------------------------------------------------------------
extern "C" void kernel_launch(void* const* d_in, const int* in_sizes, int n_in,
                              void* d_out, int out_size) {
    const float* X     = (const float*)d_in[0];
    const float* ref   = (const float*)d_in[1];
    const float* W_X   = (const float*)d_in[2];
    const float* b_X   = (const float*)d_in[3];
    const float* W_ref = (const float*)d_in[4];
    const float* b_ref = (const float*)d_in[5];
    const float* v_w   = (const float*)d_in[6];
    float* out = (float*)d_out;

    dim3 blk(256);
    xh_kernel<<<(B_ * NX_ * D_ / 4) / 256, blk>>>(X);
    transA_kernel<<<dim3(NX_ / 32, D_ / 32, 2 * B_), dim3(32, 8)>>>(X, ref);
    transW_kernel<<<dim3(H_ / 32, D_ / 32, 2), dim3(32, 8)>>>(W_X, W_ref);
    proj16_kernel<<<dim3(NX_ / 64, H_ / 64, 2 * B_), blk>>>(b_X, b_ref);
    score_kernel<<<SCORE_CTAS, blk>>>(v_w);
    colsum_kernel<<<dim3(8, NR_ / 256, B_), blk>>>();
    inv_kernel<<<(B_ * NR_) / 256, blk>>>();
    norm_kernel<<<(B_ * NX_ * NR_ / 4) / 256, blk>>>();
    out_gemm_kernel<<<dim3(D_ / 64, NR_ / 64, B_), blk>>>(out);
}

// round 13
// speedup vs baseline: 1.1790x; 1.0638x over previous
#include <cuda_runtime.h>
#include <cuda_fp16.h>

#define B_   8
#define NX_  512
#define NR_  512
#define D_   256
#define H_   256

// Scratch (device globals — no allocation allowed anywhere)
__device__ __half   g_hXT  [B_ * H_ * NX_];   // [b][h][x]  fp16
__device__ __half   g_hRT  [B_ * H_ * NR_];   // [b][h][r]  fp16
__device__ float    g_ST   [B_ * NX_ * NR_];  // [b][x][r]  exp(score), fp32
__device__ __half   g_attnT[B_ * NX_ * NR_];  // [b][x][r]  attn, fp16
__device__ __half   g_Xh   [B_ * NX_ * D_];   // [b][x][d]  X fp16 (out_gemm B)
__device__ __half   g_XT   [B_ * D_ * NX_];   // [b][d][x]  X^T fp16 (proj B)
__device__ __half   g_refT [B_ * D_ * NR_];   // [b][d][r]  ref^T fp16
__device__ __half   g_WXT  [D_ * H_];         // [d][h]     W_X^T fp16 (proj A)
__device__ __half   g_WRT  [D_ * H_];         // [d][h]     W_ref^T fp16
__device__ float    g_part [8][B_ * NR_];     // partial column sums
__device__ float    g_inv  [B_ * NR_];        // 1/colsum
__device__ unsigned g_tile;                   // dynamic tile counter for score

__device__ __forceinline__ __half2 tanh2(__half2 x) {
    __half2 y;
    asm("tanh.approx.f16x2 %0, %1;"
        : "=r"(*reinterpret_cast<unsigned*>(&y))
        : "r"(*reinterpret_cast<unsigned*>(&x)));
    return y;
}
__device__ __forceinline__ unsigned smem_u32(const void* p) {
    return (unsigned)__cvta_generic_to_shared(p);
}
#define CP16(dst, src) asm volatile("cp.async.cg.shared.global [%0], [%1], 16;" :: "r"(dst), "l"(src))
#define CP_COMMIT()    asm volatile("cp.async.commit_group;")
#define CP_WAIT1()     asm volatile("cp.async.wait_group 1;" ::: "memory")

// ---------------------------------------------------------------------------
// Prep A: Xh = fp16(X) (row layout, for out_gemm); also resets tile counter.
// ---------------------------------------------------------------------------
__global__ __launch_bounds__(256) void xh_kernel(const float* __restrict__ X) {
    if (blockIdx.x == 0 && threadIdx.x == 0) g_tile = 0u;
    int idx = blockIdx.x * 256 + threadIdx.x;
    float4 v = reinterpret_cast<const float4*>(X)[idx];
    __half2 h0 = __floats2half2_rn(v.x, v.y);
    __half2 h1 = __floats2half2_rn(v.z, v.w);
    uint2 pk = {*reinterpret_cast<unsigned*>(&h0), *reinterpret_cast<unsigned*>(&h1)};
    reinterpret_cast<uint2*>(g_Xh)[idx] = pk;
}

// ---------------------------------------------------------------------------
// Prep B: transpose activations to fp16 [d][x]: z<8 -> X -> g_XT, else ref.
// ---------------------------------------------------------------------------
__global__ __launch_bounds__(256) void transA_kernel(const float* __restrict__ X,
                                                     const float* __restrict__ ref) {
    __shared__ float s[32][33];
    int z = blockIdx.z, b = z & 7;
    const float* in = ((z < 8) ? X : ref) + (size_t)b * NX_ * D_;
    __half* out = ((z < 8) ? g_XT : g_refT) + (size_t)b * D_ * NX_;
    int x0 = blockIdx.x * 32, d0 = blockIdx.y * 32;
    int tx = threadIdx.x, ty = threadIdx.y;
#pragma unroll
    for (int l = 0; l < 4; l++)
        s[ty + l * 8][tx] = in[(size_t)(x0 + ty + l * 8) * D_ + d0 + tx];
    __syncthreads();
#pragma unroll
    for (int l = 0; l < 4; l++)
        out[(size_t)(d0 + ty + l * 8) * NX_ + x0 + tx] = __float2half_rn(s[tx][ty + l * 8]);
}

// ---------------------------------------------------------------------------
// Prep C: transpose weights to fp16 [d][h]: z=0 -> W_X, z=1 -> W_ref.
// ---------------------------------------------------------------------------
__global__ __launch_bounds__(256) void transW_kernel(const float* __restrict__ W_X,
                                                     const float* __restrict__ W_ref) {
    __shared__ float s[32][33];
    int z = blockIdx.z;
    const float* in = (z == 0) ? W_X : W_ref;
    __half* out = (z == 0) ? g_WXT : g_WRT;
    int h0 = blockIdx.x * 32, d0 = blockIdx.y * 32;
    int tx = threadIdx.x, ty = threadIdx.y;
#pragma unroll
    for (int l = 0; l < 4; l++)
        s[ty + l * 8][tx] = in[(size_t)(h0 + ty + l * 8) * D_ + d0 + tx];
    __syncthreads();
#pragma unroll
    for (int l = 0; l < 4; l++)
        out[(size_t)(d0 + ty + l * 8) * H_ + h0 + tx] = __float2half_rn(s[tx][ty + l * 8]);
}

// ---------------------------------------------------------------------------
// Phase 1: hT[b][h][x] = sum_d WT[d][h]*XT[b][d][x] + bias[h], fp16 out.
// cp.async 3-stage pipeline (wait_group 1): one load-group always in flight.
// ---------------------------------------------------------------------------
#define BUF_STRIDE 4096   // 32*64*2 bytes per stage

__global__ __launch_bounds__(256) void proj16_kernel(const float* __restrict__ b_X,
                                                     const float* __restrict__ b_ref) {
    __shared__ __half sA[3][32][64];   // WT tile  [k=d][m=h]
    __shared__ __half sB[3][32][64];   // XT tile  [k=d][n=x]
    int tid = threadIdx.x;
    int tx = tid & 15, ty = tid >> 4;
    int z = blockIdx.z, b = z & 7;
    const __half* WT = (z < 8) ? g_WXT : g_WRT;
    const __half* XT = ((z < 8) ? g_XT : g_refT) + (size_t)b * D_ * NX_;
    const float* bias = (z < 8) ? b_X : b_ref;
    __half* C = ((z < 8) ? g_hXT : g_hRT) + (size_t)b * H_ * NX_;
    int n0 = blockIdx.x * 64, m0 = blockIdx.y * 64;
    int frow = tid >> 3, fseg = tid & 7;

    unsigned dA0 = smem_u32(&sA[0][frow][fseg * 8]);
    unsigned dB0 = smem_u32(&sB[0][frow][fseg * 8]);

    float acc[4][4] = {};

    // prologue: stage 0 and 1 in flight
#pragma unroll
    for (int p = 0; p < 2; p++) {
        CP16(dA0 + p * BUF_STRIDE, &WT[(size_t)(p * 32 + frow) * H_  + m0 + fseg * 8]);
        CP16(dB0 + p * BUF_STRIDE, &XT[(size_t)(p * 32 + frow) * NX_ + n0 + fseg * 8]);
        CP_COMMIT();
    }

    const int NIT = 8;                  // K = 256
    int buf = 0, nbuf = 2;
    for (int it = 0; it < NIT; it++) {
        CP_WAIT1();                     // oldest group (buf) resolved
        __syncthreads();
        if (it + 2 < NIT) {             // refill buffer computed 2 iters ago
            int kk = (it + 2) * 32;
            CP16(dA0 + nbuf * BUF_STRIDE, &WT[(size_t)(kk + frow) * H_  + m0 + fseg * 8]);
            CP16(dB0 + nbuf * BUF_STRIDE, &XT[(size_t)(kk + frow) * NX_ + n0 + fseg * 8]);
            CP_COMMIT();
        }
#pragma unroll
        for (int k8 = 0; k8 < 32; k8 += 8) {
            __half2 acc2[4][2] = {};
#pragma unroll
            for (int k = 0; k < 8; k++) {
                int kk = k8 + k;
                uint2 au = *reinterpret_cast<const uint2*>(&sA[buf][kk][ty * 4]);
                uint2 bu = *reinterpret_cast<const uint2*>(&sB[buf][kk][tx * 4]);
                const __half* ah = reinterpret_cast<const __half*>(&au);
                __half2 b2[2] = {*reinterpret_cast<__half2*>(&bu.x),
                                 *reinterpret_cast<__half2*>(&bu.y)};
#pragma unroll
                for (int i = 0; i < 4; i++) {
                    __half2 ai = __half2half2(ah[i]);
#pragma unroll
                    for (int j2 = 0; j2 < 2; j2++)
                        acc2[i][j2] = __hfma2(ai, b2[j2], acc2[i][j2]);
                }
            }
#pragma unroll
            for (int i = 0; i < 4; i++)
#pragma unroll
                for (int j2 = 0; j2 < 2; j2++) {
                    float2 f = __half22float2(acc2[i][j2]);
                    acc[i][2 * j2 + 0] += f.x;
                    acc[i][2 * j2 + 1] += f.y;
                }
        }
        __syncthreads();
        buf = (buf + 1) % 3; nbuf = (nbuf + 1) % 3;
    }

#pragma unroll
    for (int i = 0; i < 4; i++) {
        int h = m0 + ty * 4 + i;
        float bb = bias[h];
        __half2 p0 = __floats2half2_rn(acc[i][0] + bb, acc[i][1] + bb);
        __half2 p1 = __floats2half2_rn(acc[i][2] + bb, acc[i][3] + bb);
        uint2 pk = {*reinterpret_cast<unsigned*>(&p0), *reinterpret_cast<unsigned*>(&p1)};
        *reinterpret_cast<uint2*>(&C[(size_t)h * NX_ + n0 + tx * 4]) = pk;
    }
}

// ---------------------------------------------------------------------------
// Phase 2: S_T[b][x][r] = exp( sum_h v[h]*tanh(hX[b][h][x] + hR[b][h][r]) )
// Persistent 296 CTAs. Tile now 64x * 32r (1024 tiles) -> makespan tail ~3%
// instead of 15%. Per-(x,r) arithmetic and flush order IDENTICAL to R12.
// ---------------------------------------------------------------------------
#define NTILES      1024
#define SCORE_CTAS  296

__global__ __launch_bounds__(256) void score_kernel(const float* __restrict__ vw) {
    __shared__ __half2  sX2[32][64];    // [h][x] as (x,x)   8 KB
    __shared__ __half   sR [32][32];    // [h][r]            2 KB
    __shared__ __half2  sv2[H_];
    __shared__ unsigned s_tile;

    int tid = threadIdx.x;
    int tx = tid & 15, ty = tid >> 4;
    int frow = tid >> 3, fseg = tid & 7;

    sv2[tid] = __half2half2(__float2half_rn(vw[tid]));

    for (;;) {
        __syncthreads();
        if (tid == 0) s_tile = atomicAdd(&g_tile, 1u);
        __syncthreads();
        unsigned t = s_tile;
        if (t >= NTILES) break;
        int b  = (int)(t >> 7);
        int r0 = (int)((t >> 3) & 15) * 32;
        int x0 = (int)(t & 7) * 64;
        const __half* hXb = g_hXT + (size_t)b * H_ * NX_;
        const __half* hRb = g_hRT + (size_t)b * H_ * NR_;

        float acc[4][2] = {};   // [i: x][r pair]

        for (int h0 = 0; h0 < H_; h0 += 32) {
            uint4 xv = *reinterpret_cast<const uint4*>(&hXb[(size_t)(h0 + frow) * NX_ + x0 + fseg * 8]);
            const __half* xh = reinterpret_cast<const __half*>(&xv);
            __half2* dst = &sX2[frow][fseg * 8];
#pragma unroll
            for (int k = 0; k < 8; k++) dst[k] = __half2half2(xh[k]);
            *reinterpret_cast<uint2*>(&sR[frow][fseg * 4]) =
                *reinterpret_cast<const uint2*>(&hRb[(size_t)(h0 + frow) * NR_ + r0 + fseg * 4]);
            __syncthreads();

#pragma unroll
            for (int hh = 0; hh < 32; hh += 8) {
                __half2 a2[4] = {};
#pragma unroll
                for (int h = 0; h < 8; h++) {
                    int hc = hh + h;
                    __half2 v2 = sv2[h0 + hc];
                    uint4 xu = *reinterpret_cast<const uint4*>(&sX2[hc][ty * 4]);
                    __half2 rr = *reinterpret_cast<const __half2*>(&sR[hc][tx * 2]);
                    __half2 x2[4] = {*reinterpret_cast<__half2*>(&xu.x),
                                     *reinterpret_cast<__half2*>(&xu.y),
                                     *reinterpret_cast<__half2*>(&xu.z),
                                     *reinterpret_cast<__half2*>(&xu.w)};
#pragma unroll
                    for (int i = 0; i < 4; i++)
                        a2[i] = __hfma2(v2, tanh2(__hadd2(x2[i], rr)), a2[i]);
                }
#pragma unroll
                for (int i = 0; i < 4; i++) {
                    float2 f = __half22float2(a2[i]);
                    acc[i][0] += f.x;
                    acc[i][1] += f.y;
                }
            }
            __syncthreads();
        }

        float* Sb = g_ST + (size_t)b * NX_ * NR_;
#pragma unroll
        for (int i = 0; i < 4; i++) {
            float2 o = {__expf(acc[i][0]), __expf(acc[i][1])};
            *reinterpret_cast<float2*>(&Sb[(size_t)(x0 + ty * 4 + i) * NR_ + r0 + tx * 2]) = o;
        }
    }
}

// ---------------------------------------------------------------------------
// Phase 3a: partial column sums over x. grid (8, NR/256, B), block 256.
// ---------------------------------------------------------------------------
__global__ __launch_bounds__(256) void colsum_kernel() {
    int seg = blockIdx.x, b = blockIdx.z;
    int r = blockIdx.y * 256 + threadIdx.x;
    const float* base = g_ST + (size_t)b * NX_ * NR_ + r;
    float s = 0.0f;
    int x0 = seg * 64;
#pragma unroll 8
    for (int x = x0; x < x0 + 64; x++)
        s += base[(size_t)x * NR_];
    g_part[seg][b * NR_ + r] = s;
}

// Phase 3b: inv = 1/colsum. 16 blocks x 256.
__global__ __launch_bounds__(256) void inv_kernel() {
    int i = blockIdx.x * 256 + threadIdx.x;
    float s = 0.0f;
#pragma unroll
    for (int p = 0; p < 8; p++) s += g_part[p][i];
    g_inv[i] = 1.0f / s;
}

// Phase 3c: attn_T = ST * inv, fp16 out. 2048 blocks x 256.
__global__ __launch_bounds__(256) void norm_kernel() {
    int flat4 = blockIdx.x * 256 + threadIdx.x;
    int idx = flat4 * 4;
    int r = idx & (NR_ - 1);
    int b = idx >> 18;
    float4 s = reinterpret_cast<const float4*>(g_ST)[flat4];
    float4 iv = *reinterpret_cast<const float4*>(&g_inv[b * NR_ + r]);
    __half2 h0 = __floats2half2_rn(s.x * iv.x, s.y * iv.y);
    __half2 h1 = __floats2half2_rn(s.z * iv.z, s.w * iv.w);
    uint2 pk = {*reinterpret_cast<unsigned*>(&h0), *reinterpret_cast<unsigned*>(&h1)};
    reinterpret_cast<uint2*>(g_attnT)[flat4] = pk;
}

// ---------------------------------------------------------------------------
// Phase 4: out[b][r][d] = sum_x attn_T[b][x][r] * Xh[b][x][d]
// cp.async 3-stage pipeline, HFMA2, fp32 flush every 8k (R12 numerics).
// ---------------------------------------------------------------------------
__global__ __launch_bounds__(256) void out_gemm_kernel(float* __restrict__ out) {
    __shared__ __half sA[3][32][64];
    __shared__ __half sB[3][32][64];
    int tid = threadIdx.x;
    int tx = tid & 15, ty = tid >> 4;
    int n0 = blockIdx.x * 64, m0 = blockIdx.y * 64, b = blockIdx.z;
    const __half* Ab = g_attnT + (size_t)b * NX_ * NR_;
    const __half* Bb = g_Xh    + (size_t)b * NX_ * D_;
    int frow = tid >> 3, fseg = tid & 7;

    unsigned dA0 = smem_u32(&sA[0][frow][fseg * 8]);
    unsigned dB0 = smem_u32(&sB[0][frow][fseg * 8]);

    float acc[4][4] = {};

#pragma unroll
    for (int p = 0; p < 2; p++) {
        CP16(dA0 + p * BUF_STRIDE, &Ab[(size_t)(p * 32 + frow) * NR_ + m0 + fseg * 8]);
        CP16(dB0 + p * BUF_STRIDE, &Bb[(size_t)(p * 32 + frow) * D_  + n0 + fseg * 8]);
        CP_COMMIT();
    }

    const int NIT = 16;                 // K = 512
    int buf = 0, nbuf = 2;
    for (int it = 0; it < NIT; it++) {
        CP_WAIT1();
        __syncthreads();
        if (it + 2 < NIT) {
            int kk = (it + 2) * 32;
            CP16(dA0 + nbuf * BUF_STRIDE, &Ab[(size_t)(kk + frow) * NR_ + m0 + fseg * 8]);
            CP16(dB0 + nbuf * BUF_STRIDE, &Bb[(size_t)(kk + frow) * D_  + n0 + fseg * 8]);
            CP_COMMIT();
        }
#pragma unroll
        for (int k8 = 0; k8 < 32; k8 += 8) {
            __half2 acc2[4][2] = {};
#pragma unroll
            for (int k = 0; k < 8; k++) {
                int kk = k8 + k;
                uint2 au = *reinterpret_cast<const uint2*>(&sA[buf][kk][ty * 4]);
                uint2 bu = *reinterpret_cast<const uint2*>(&sB[buf][kk][tx * 4]);
                const __half* ah = reinterpret_cast<const __half*>(&au);
                __half2 b2[2] = {*reinterpret_cast<__half2*>(&bu.x),
                                 *reinterpret_cast<__half2*>(&bu.y)};
#pragma unroll
                for (int i = 0; i < 4; i++) {
                    __half2 ai = __half2half2(ah[i]);
#pragma unroll
                    for (int j2 = 0; j2 < 2; j2++)
                        acc2[i][j2] = __hfma2(ai, b2[j2], acc2[i][j2]);
                }
            }
#pragma unroll
            for (int i = 0; i < 4; i++)
#pragma unroll
                for (int j2 = 0; j2 < 2; j2++) {
                    float2 f = __half22float2(acc2[i][j2]);
                    acc[i][2 * j2 + 0] += f.x;
                    acc[i][2 * j2 + 1] += f.y;
                }
        }
        __syncthreads();
        buf = (buf + 1) % 3; nbuf = (nbuf + 1) % 3;
    }

#pragma unroll
    for (int i = 0; i < 4; i++) {
        float4 o = {acc[i][0], acc[i][1], acc[i][2], acc[i][3]};
        *reinterpret_cast<float4*>(&out[((size_t)b * NR_ + m0 + ty * 4 + i) * D_ + n0 + tx * 4]) = o;
    }
}

// ---------------------------------------------------------------------------
// Launch (graph-capturable, allocation-free).
// Inputs: X, ref, W_X, b_X, W_ref, b_ref, v_w, v_b (v_b drops out of softmax).
// ---------------------------------------------------------------------------
extern "C" void kernel_launch(void* const* d_in, const int* in_sizes, int n_in,
                              void* d_out, int out_size) {
    const float* X     = (const float*)d_in[0];
    const float* ref   = (const float*)d_in[1];
    const float* W_X   = (const float*)d_in[2];
    const float* b_X   = (const float*)d_in[3];
    const float* W_ref = (const float*)d_in[4];
    const float* b_ref = (const float*)d_in[5];
    const float* v_w   = (const float*)d_in[6];
    float* out = (float*)d_out;

    dim3 blk(256);
    xh_kernel<<<(B_ * NX_ * D_ / 4) / 256, blk>>>(X);
    transA_kernel<<<dim3(NX_ / 32, D_ / 32, 2 * B_), dim3(32, 8)>>>(X, ref);
    transW_kernel<<<dim3(H_ / 32, D_ / 32, 2), dim3(32, 8)>>>(W_X, W_ref);
    proj16_kernel<<<dim3(NX_ / 64, H_ / 64, 2 * B_), blk>>>(b_X, b_ref);
    score_kernel<<<SCORE_CTAS, blk>>>(v_w);
    colsum_kernel<<<dim3(8, NR_ / 256, B_), blk>>>();
    inv_kernel<<<(B_ * NR_) / 256, blk>>>();
    norm_kernel<<<(B_ * NX_ * NR_ / 4) / 256, blk>>>();
    out_gemm_kernel<<<dim3(D_ / 64, NR_ / 64, B_), blk>>>(out);
}

// round 14
// speedup vs baseline: 1.2005x; 1.0182x over previous
#include <cuda_runtime.h>
#include <cuda_fp16.h>

#define B_   8
#define NX_  512
#define NR_  512
#define D_   256
#define H_   256

// Scratch (device globals — no allocation allowed anywhere)
__device__ __half   g_hXT  [B_ * H_ * NX_];   // [b][h][x]  fp16
__device__ __half   g_hRT  [B_ * H_ * NR_];   // [b][h][r]  fp16
__device__ float    g_ST   [B_ * NX_ * NR_];  // [b][x][r]  exp(score), fp32
__device__ __half   g_attnT[B_ * NX_ * NR_];  // [b][x][r]  attn, fp16
__device__ __half   g_Xh   [B_ * NX_ * D_];   // [b][x][d]  X fp16 (out_gemm B)
__device__ __half   g_XT   [B_ * D_ * NX_];   // [b][d][x]  X^T fp16 (proj B)
__device__ __half   g_refT [B_ * D_ * NR_];   // [b][d][r]  ref^T fp16
__device__ __half   g_WXT  [D_ * H_];         // [d][h]     W_X^T fp16 (proj A)
__device__ __half   g_WRT  [D_ * H_];         // [d][h]     W_ref^T fp16
__device__ float    g_part [8][B_ * NR_];     // partial column sums
__device__ float    g_inv  [B_ * NR_];        // 1/colsum
__device__ unsigned g_tile;                   // dynamic tile counter for score

__device__ __forceinline__ __half2 tanh2(__half2 x) {
    __half2 y;
    asm("tanh.approx.f16x2 %0, %1;"
        : "=r"(*reinterpret_cast<unsigned*>(&y))
        : "r"(*reinterpret_cast<unsigned*>(&x)));
    return y;
}
__device__ __forceinline__ unsigned smem_u32(const void* p) {
    return (unsigned)__cvta_generic_to_shared(p);
}
#define CP16(dst, src) asm volatile("cp.async.cg.shared.global [%0], [%1], 16;" :: "r"(dst), "l"(src))
#define CP_COMMIT()    asm volatile("cp.async.commit_group;")
#define CP_WAIT1()     asm volatile("cp.async.wait_group 1;" ::: "memory")
#define BUF_STRIDE 4096   // 32*64*2 bytes per stage

// ---------------------------------------------------------------------------
// Prep A: Xh = fp16(X); also resets tile counter.
// ---------------------------------------------------------------------------
__global__ __launch_bounds__(256) void xh_kernel(const float* __restrict__ X) {
    if (blockIdx.x == 0 && threadIdx.x == 0) g_tile = 0u;
    int idx = blockIdx.x * 256 + threadIdx.x;
    float4 v = reinterpret_cast<const float4*>(X)[idx];
    __half2 h0 = __floats2half2_rn(v.x, v.y);
    __half2 h1 = __floats2half2_rn(v.z, v.w);
    uint2 pk = {*reinterpret_cast<unsigned*>(&h0), *reinterpret_cast<unsigned*>(&h1)};
    reinterpret_cast<uint2*>(g_Xh)[idx] = pk;
}

// ---------------------------------------------------------------------------
// Prep B: transpose activations to fp16 [d][x]: z<8 -> X -> g_XT, else ref.
// ---------------------------------------------------------------------------
__global__ __launch_bounds__(256) void transA_kernel(const float* __restrict__ X,
                                                     const float* __restrict__ ref) {
    __shared__ float s[32][33];
    int z = blockIdx.z, b = z & 7;
    const float* in = ((z < 8) ? X : ref) + (size_t)b * NX_ * D_;
    __half* out = ((z < 8) ? g_XT : g_refT) + (size_t)b * D_ * NX_;
    int x0 = blockIdx.x * 32, d0 = blockIdx.y * 32;
    int tx = threadIdx.x, ty = threadIdx.y;
#pragma unroll
    for (int l = 0; l < 4; l++)
        s[ty + l * 8][tx] = in[(size_t)(x0 + ty + l * 8) * D_ + d0 + tx];
    __syncthreads();
#pragma unroll
    for (int l = 0; l < 4; l++)
        out[(size_t)(d0 + ty + l * 8) * NX_ + x0 + tx] = __float2half_rn(s[tx][ty + l * 8]);
}

// ---------------------------------------------------------------------------
// Prep C: transpose weights to fp16 [d][h]: z=0 -> W_X, z=1 -> W_ref.
// ---------------------------------------------------------------------------
__global__ __launch_bounds__(256) void transW_kernel(const float* __restrict__ W_X,
                                                     const float* __restrict__ W_ref) {
    __shared__ float s[32][33];
    int z = blockIdx.z;
    const float* in = (z == 0) ? W_X : W_ref;
    __half* out = (z == 0) ? g_WXT : g_WRT;
    int h0 = blockIdx.x * 32, d0 = blockIdx.y * 32;
    int tx = threadIdx.x, ty = threadIdx.y;
#pragma unroll
    for (int l = 0; l < 4; l++)
        s[ty + l * 8][tx] = in[(size_t)(h0 + ty + l * 8) * D_ + d0 + tx];
    __syncthreads();
#pragma unroll
    for (int l = 0; l < 4; l++)
        out[(size_t)(d0 + ty + l * 8) * H_ + h0 + tx] = __float2half_rn(s[tx][ty + l * 8]);
}

// ---------------------------------------------------------------------------
// Phase 1: hT[b][h][x] = sum_d WT[d][h]*XT[b][d][x] + bias[h], fp16 out.
// Retiled: 128 threads, 4m x 8n per thread. Per k-step: 1 LDS.64 + 1 LDS.128
// (warp-broadcast, conflict-free) feeding 16 HFMA2 -> ~73% HFMA2 issue mix.
// Per-element k-order and 8-k flush boundaries identical to R13.
// ---------------------------------------------------------------------------
__global__ __launch_bounds__(128) void proj16_kernel(const float* __restrict__ b_X,
                                                     const float* __restrict__ b_ref) {
    __shared__ __half sA[3][32][64];   // WT tile  [k=d][m=h]
    __shared__ __half sB[3][32][64];   // XT tile  [k=d][n=x]
    int tid = threadIdx.x;
    int tx = tid & 7, ty = tid >> 3;        // tx: n-group (8x8=64), ty: m-group (16x4=64)
    int z = blockIdx.z, b = z & 7;
    const __half* WT = (z < 8) ? g_WXT : g_WRT;
    const __half* XT = ((z < 8) ? g_XT : g_refT) + (size_t)b * D_ * NX_;
    const float* bias = (z < 8) ? b_X : b_ref;
    __half* C = ((z < 8) ? g_hXT : g_hRT) + (size_t)b * H_ * NX_;
    int n0 = blockIdx.x * 64, m0 = blockIdx.y * 64;
    int frow = tid >> 2, fs = tid & 3;       // 32 rows, 4 thr/row, segs fs and fs+4

    unsigned dAa = smem_u32(&sA[0][frow][fs * 8]);
    unsigned dAb = smem_u32(&sA[0][frow][fs * 8 + 32]);
    unsigned dBa = smem_u32(&sB[0][frow][fs * 8]);
    unsigned dBb = smem_u32(&sB[0][frow][fs * 8 + 32]);

    float acc[4][8] = {};

#pragma unroll
    for (int p = 0; p < 2; p++) {
        const __half* wr = &WT[(size_t)(p * 32 + frow) * H_  + m0];
        const __half* xr = &XT[(size_t)(p * 32 + frow) * NX_ + n0];
        CP16(dAa + p * BUF_STRIDE, wr + fs * 8);
        CP16(dAb + p * BUF_STRIDE, wr + fs * 8 + 32);
        CP16(dBa + p * BUF_STRIDE, xr + fs * 8);
        CP16(dBb + p * BUF_STRIDE, xr + fs * 8 + 32);
        CP_COMMIT();
    }

    const int NIT = 8;                  // K = 256
    int buf = 0, nbuf = 2;
    for (int it = 0; it < NIT; it++) {
        CP_WAIT1();
        __syncthreads();
        if (it + 2 < NIT) {
            int kk = (it + 2) * 32;
            const __half* wr = &WT[(size_t)(kk + frow) * H_  + m0];
            const __half* xr = &XT[(size_t)(kk + frow) * NX_ + n0];
            CP16(dAa + nbuf * BUF_STRIDE, wr + fs * 8);
            CP16(dAb + nbuf * BUF_STRIDE, wr + fs * 8 + 32);
            CP16(dBa + nbuf * BUF_STRIDE, xr + fs * 8);
            CP16(dBb + nbuf * BUF_STRIDE, xr + fs * 8 + 32);
            CP_COMMIT();
        }
#pragma unroll
        for (int k8 = 0; k8 < 32; k8 += 8) {
            __half2 acc2[4][4] = {};
#pragma unroll
            for (int k = 0; k < 8; k++) {
                int kk = k8 + k;
                uint2 au = *reinterpret_cast<const uint2*>(&sA[buf][kk][ty * 4]);
                uint4 bu = *reinterpret_cast<const uint4*>(&sB[buf][kk][tx * 8]);
                const __half* ah = reinterpret_cast<const __half*>(&au);
                __half2 b2[4] = {*reinterpret_cast<__half2*>(&bu.x),
                                 *reinterpret_cast<__half2*>(&bu.y),
                                 *reinterpret_cast<__half2*>(&bu.z),
                                 *reinterpret_cast<__half2*>(&bu.w)};
#pragma unroll
                for (int i = 0; i < 4; i++) {
                    __half2 ai = __half2half2(ah[i]);
#pragma unroll
                    for (int j = 0; j < 4; j++)
                        acc2[i][j] = __hfma2(ai, b2[j], acc2[i][j]);
                }
            }
#pragma unroll
            for (int i = 0; i < 4; i++)
#pragma unroll
                for (int j = 0; j < 4; j++) {
                    float2 f = __half22float2(acc2[i][j]);
                    acc[i][2 * j + 0] += f.x;
                    acc[i][2 * j + 1] += f.y;
                }
        }
        __syncthreads();
        buf = (buf + 1) % 3; nbuf = (nbuf + 1) % 3;
    }

#pragma unroll
    for (int i = 0; i < 4; i++) {
        int h = m0 + ty * 4 + i;
        float bb = bias[h];
        __half2 p[4];
#pragma unroll
        for (int j = 0; j < 4; j++)
            p[j] = __floats2half2_rn(acc[i][2 * j] + bb, acc[i][2 * j + 1] + bb);
        uint4 pk = {*reinterpret_cast<unsigned*>(&p[0]), *reinterpret_cast<unsigned*>(&p[1]),
                    *reinterpret_cast<unsigned*>(&p[2]), *reinterpret_cast<unsigned*>(&p[3])};
        *reinterpret_cast<uint4*>(&C[(size_t)h * NX_ + n0 + tx * 8]) = pk;
    }
}

// ---------------------------------------------------------------------------
// Phase 2: S_T[b][x][r] = exp( sum_h v[h]*tanh(hX[b][h][x] + hR[b][h][r]) )
// Persistent, now 444 CTAs (3/SM -> 24 warps/SM hides LDS under MUFU shadow).
// 64x * 32r tiles (1024). Per-(x,r) arithmetic IDENTICAL to R13.
// ---------------------------------------------------------------------------
#define NTILES      1024
#define SCORE_CTAS  444

__global__ __launch_bounds__(256) void score_kernel(const float* __restrict__ vw) {
    __shared__ __half2  sX2[32][64];    // [h][x] as (x,x)   8 KB
    __shared__ __half   sR [32][32];    // [h][r]            2 KB
    __shared__ __half2  sv2[H_];
    __shared__ unsigned s_tile;

    int tid = threadIdx.x;
    int tx = tid & 15, ty = tid >> 4;
    int frow = tid >> 3, fseg = tid & 7;

    sv2[tid] = __half2half2(__float2half_rn(vw[tid]));

    for (;;) {
        __syncthreads();
        if (tid == 0) s_tile = atomicAdd(&g_tile, 1u);
        __syncthreads();
        unsigned t = s_tile;
        if (t >= NTILES) break;
        int b  = (int)(t >> 7);
        int r0 = (int)((t >> 3) & 15) * 32;
        int x0 = (int)(t & 7) * 64;
        const __half* hXb = g_hXT + (size_t)b * H_ * NX_;
        const __half* hRb = g_hRT + (size_t)b * H_ * NR_;

        float acc[4][2] = {};

        for (int h0 = 0; h0 < H_; h0 += 32) {
            uint4 xv = *reinterpret_cast<const uint4*>(&hXb[(size_t)(h0 + frow) * NX_ + x0 + fseg * 8]);
            const __half* xh = reinterpret_cast<const __half*>(&xv);
            __half2* dst = &sX2[frow][fseg * 8];
#pragma unroll
            for (int k = 0; k < 8; k++) dst[k] = __half2half2(xh[k]);
            *reinterpret_cast<uint2*>(&sR[frow][fseg * 4]) =
                *reinterpret_cast<const uint2*>(&hRb[(size_t)(h0 + frow) * NR_ + r0 + fseg * 4]);
            __syncthreads();

#pragma unroll
            for (int hh = 0; hh < 32; hh += 8) {
                __half2 a2[4] = {};
#pragma unroll
                for (int h = 0; h < 8; h++) {
                    int hc = hh + h;
                    __half2 v2 = sv2[h0 + hc];
                    uint4 xu = *reinterpret_cast<const uint4*>(&sX2[hc][ty * 4]);
                    __half2 rr = *reinterpret_cast<const __half2*>(&sR[hc][tx * 2]);
                    __half2 x2[4] = {*reinterpret_cast<__half2*>(&xu.x),
                                     *reinterpret_cast<__half2*>(&xu.y),
                                     *reinterpret_cast<__half2*>(&xu.z),
                                     *reinterpret_cast<__half2*>(&xu.w)};
#pragma unroll
                    for (int i = 0; i < 4; i++)
                        a2[i] = __hfma2(v2, tanh2(__hadd2(x2[i], rr)), a2[i]);
                }
#pragma unroll
                for (int i = 0; i < 4; i++) {
                    float2 f = __half22float2(a2[i]);
                    acc[i][0] += f.x;
                    acc[i][1] += f.y;
                }
            }
            __syncthreads();
        }

        float* Sb = g_ST + (size_t)b * NX_ * NR_;
#pragma unroll
        for (int i = 0; i < 4; i++) {
            float2 o = {__expf(acc[i][0]), __expf(acc[i][1])};
            *reinterpret_cast<float2*>(&Sb[(size_t)(x0 + ty * 4 + i) * NR_ + r0 + tx * 2]) = o;
        }
    }
}

// ---------------------------------------------------------------------------
// Phase 3a: partial column sums over x. grid (8, NR/256, B), block 256.
// ---------------------------------------------------------------------------
__global__ __launch_bounds__(256) void colsum_kernel() {
    int seg = blockIdx.x, b = blockIdx.z;
    int r = blockIdx.y * 256 + threadIdx.x;
    const float* base = g_ST + (size_t)b * NX_ * NR_ + r;
    float s = 0.0f;
    int x0 = seg * 64;
#pragma unroll 8
    for (int x = x0; x < x0 + 64; x++)
        s += base[(size_t)x * NR_];
    g_part[seg][b * NR_ + r] = s;
}

// Phase 3b: inv = 1/colsum. 16 blocks x 256.
__global__ __launch_bounds__(256) void inv_kernel() {
    int i = blockIdx.x * 256 + threadIdx.x;
    float s = 0.0f;
#pragma unroll
    for (int p = 0; p < 8; p++) s += g_part[p][i];
    g_inv[i] = 1.0f / s;
}

// Phase 3c: attn_T = ST * inv, fp16 out. 2048 blocks x 256.
__global__ __launch_bounds__(256) void norm_kernel() {
    int flat4 = blockIdx.x * 256 + threadIdx.x;
    int idx = flat4 * 4;
    int r = idx & (NR_ - 1);
    int b = idx >> 18;
    float4 s = reinterpret_cast<const float4*>(g_ST)[flat4];
    float4 iv = *reinterpret_cast<const float4*>(&g_inv[b * NR_ + r]);
    __half2 h0 = __floats2half2_rn(s.x * iv.x, s.y * iv.y);
    __half2 h1 = __floats2half2_rn(s.z * iv.z, s.w * iv.w);
    uint2 pk = {*reinterpret_cast<unsigned*>(&h0), *reinterpret_cast<unsigned*>(&h1)};
    reinterpret_cast<uint2*>(g_attnT)[flat4] = pk;
}

// ---------------------------------------------------------------------------
// Phase 4: out[b][r][d] = sum_x attn_T[b][x][r] * Xh[b][x][d]
// cp.async 3-stage pipeline, HFMA2, fp32 flush every 8k (R13 numerics).
// ---------------------------------------------------------------------------
__global__ __launch_bounds__(256) void out_gemm_kernel(float* __restrict__ out) {
    __shared__ __half sA[3][32][64];
    __shared__ __half sB[3][32][64];
    int tid = threadIdx.x;
    int tx = tid & 15, ty = tid >> 4;
    int n0 = blockIdx.x * 64, m0 = blockIdx.y * 64, b = blockIdx.z;
    const __half* Ab = g_attnT + (size_t)b * NX_ * NR_;
    const __half* Bb = g_Xh    + (size_t)b * NX_ * D_;
    int frow = tid >> 3, fseg = tid & 7;

    unsigned dA0 = smem_u32(&sA[0][frow][fseg * 8]);
    unsigned dB0 = smem_u32(&sB[0][frow][fseg * 8]);

    float acc[4][4] = {};

#pragma unroll
    for (int p = 0; p < 2; p++) {
        CP16(dA0 + p * BUF_STRIDE, &Ab[(size_t)(p * 32 + frow) * NR_ + m0 + fseg * 8]);
        CP16(dB0 + p * BUF_STRIDE, &Bb[(size_t)(p * 32 + frow) * D_  + n0 + fseg * 8]);
        CP_COMMIT();
    }

    const int NIT = 16;                 // K = 512
    int buf = 0, nbuf = 2;
    for (int it = 0; it < NIT; it++) {
        CP_WAIT1();
        __syncthreads();
        if (it + 2 < NIT) {
            int kk = (it + 2) * 32;
            CP16(dA0 + nbuf * BUF_STRIDE, &Ab[(size_t)(kk + frow) * NR_ + m0 + fseg * 8]);
            CP16(dB0 + nbuf * BUF_STRIDE, &Bb[(size_t)(kk + frow) * D_  + n0 + fseg * 8]);
            CP_COMMIT();
        }
#pragma unroll
        for (int k8 = 0; k8 < 32; k8 += 8) {
            __half2 acc2[4][2] = {};
#pragma unroll
            for (int k = 0; k < 8; k++) {
                int kk = k8 + k;
                uint2 au = *reinterpret_cast<const uint2*>(&sA[buf][kk][ty * 4]);
                uint2 bu = *reinterpret_cast<const uint2*>(&sB[buf][kk][tx * 4]);
                const __half* ah = reinterpret_cast<const __half*>(&au);
                __half2 b2[2] = {*reinterpret_cast<__half2*>(&bu.x),
                                 *reinterpret_cast<__half2*>(&bu.y)};
#pragma unroll
                for (int i = 0; i < 4; i++) {
                    __half2 ai = __half2half2(ah[i]);
#pragma unroll
                    for (int j2 = 0; j2 < 2; j2++)
                        acc2[i][j2] = __hfma2(ai, b2[j2], acc2[i][j2]);
                }
            }
#pragma unroll
            for (int i = 0; i < 4; i++)
#pragma unroll
                for (int j2 = 0; j2 < 2; j2++) {
                    float2 f = __half22float2(acc2[i][j2]);
                    acc[i][2 * j2 + 0] += f.x;
                    acc[i][2 * j2 + 1] += f.y;
                }
        }
        __syncthreads();
        buf = (buf + 1) % 3; nbuf = (nbuf + 1) % 3;
    }

#pragma unroll
    for (int i = 0; i < 4; i++) {
        float4 o = {acc[i][0], acc[i][1], acc[i][2], acc[i][3]};
        *reinterpret_cast<float4*>(&out[((size_t)b * NR_ + m0 + ty * 4 + i) * D_ + n0 + tx * 4]) = o;
    }
}

// ---------------------------------------------------------------------------
// Launch (graph-capturable, allocation-free).
// Inputs: X, ref, W_X, b_X, W_ref, b_ref, v_w, v_b (v_b drops out of softmax).
// ---------------------------------------------------------------------------
extern "C" void kernel_launch(void* const* d_in, const int* in_sizes, int n_in,
                              void* d_out, int out_size) {
    const float* X     = (const float*)d_in[0];
    const float* ref   = (const float*)d_in[1];
    const float* W_X   = (const float*)d_in[2];
    const float* b_X   = (const float*)d_in[3];
    const float* W_ref = (const float*)d_in[4];
    const float* b_ref = (const float*)d_in[5];
    const float* v_w   = (const float*)d_in[6];
    float* out = (float*)d_out;

    dim3 blk(256);
    xh_kernel<<<(B_ * NX_ * D_ / 4) / 256, blk>>>(X);
    transA_kernel<<<dim3(NX_ / 32, D_ / 32, 2 * B_), dim3(32, 8)>>>(X, ref);
    transW_kernel<<<dim3(H_ / 32, D_ / 32, 2), dim3(32, 8)>>>(W_X, W_ref);
    proj16_kernel<<<dim3(NX_ / 64, H_ / 64, 2 * B_), 128>>>(b_X, b_ref);
    score_kernel<<<SCORE_CTAS, blk>>>(v_w);
    colsum_kernel<<<dim3(8, NR_ / 256, B_), blk>>>();
    inv_kernel<<<(B_ * NR_) / 256, blk>>>();
    norm_kernel<<<(B_ * NX_ * NR_ / 4) / 256, blk>>>();
    out_gemm_kernel<<<dim3(D_ / 64, NR_ / 64, B_), blk>>>(out);
}

// round 17
// speedup vs baseline: 1.4469x; 1.2053x over previous
#include <cuda_runtime.h>
#include <cuda_fp16.h>
#include <cstdint>

#define B_   8
#define NX_  512
#define NR_  512
#define D_   256
#define H_   256

// Scratch (device globals — no allocation allowed anywhere; only ever
// referenced from DEVICE code, never as host-side kernel arguments)
__device__ __half   g_Wh  [2 * H_ * D_];      // [side][h][d] fp16 weights
__device__ __half   g_Xh  [B_ * NX_ * D_];    // [b][x][d]    fp16 X
__device__ __half   g_refh[B_ * NR_ * D_];    // [b][r][d]    fp16 ref
__device__ __half   g_XT  [B_ * D_ * NX_];    // [b][d][x]    fp16 X^T (out B operand)
__device__ __half   g_hXT [B_ * H_ * NX_];    // [b][h][x]    fp16 proj result
__device__ __half   g_hRT [B_ * H_ * NR_];    // [b][h][r]
__device__ float    g_S   [B_ * NR_ * NX_];   // [b][r][x]    exp(score) fp32
__device__ __half   g_attn[B_ * NR_ * NX_];   // [b][r][x]    attn fp16
__device__ unsigned g_tile;

__device__ __forceinline__ unsigned smem_u32(const void* p) {
    return (unsigned)__cvta_generic_to_shared(p);
}

#define LDSM_X4(r0, r1, r2, r3, addr)                                        \
    asm volatile("ldmatrix.sync.aligned.m8n8.x4.shared.b16 {%0,%1,%2,%3}, [%4];" \
        : "=r"(r0), "=r"(r1), "=r"(r2), "=r"(r3) : "r"(addr))

#define MMA16816(c, a, b)                                                    \
    asm volatile("mma.sync.aligned.m16n8k16.row.col.f32.f16.f16.f32 "        \
        "{%0,%1,%2,%3}, {%4,%5,%6,%7}, {%8,%9}, {%0,%1,%2,%3};"              \
        : "+f"((c)[0]), "+f"((c)[1]), "+f"((c)[2]), "+f"((c)[3])             \
        : "r"((a)[0]), "r"((a)[1]), "r"((a)[2]), "r"((a)[3]),                \
          "r"((b)[0]), "r"((b)[1]))

// ---------------------------------------------------------------------------
// Prep: flat fp32 -> fp16 convert. Destination resolved IN DEVICE CODE
// (which: 0=g_Xh, 1=g_refh, 2=g_Wh[W_X], 3=g_Wh[W_ref]).
// ---------------------------------------------------------------------------
__global__ __launch_bounds__(256) void f2h_kernel(const float* __restrict__ src,
                                                  int which) {
    __half* dst;
    switch (which) {
        case 0:  dst = g_Xh; break;
        case 1:  dst = g_refh; break;
        case 2:  dst = g_Wh; break;
        default: dst = g_Wh + H_ * D_; break;
    }
    int idx = blockIdx.x * 256 + threadIdx.x;
    float4 v = reinterpret_cast<const float4*>(src)[idx];
    __half2 h0 = __floats2half2_rn(v.x, v.y);
    __half2 h1 = __floats2half2_rn(v.z, v.w);
    uint2 pk = {*reinterpret_cast<unsigned*>(&h0), *reinterpret_cast<unsigned*>(&h1)};
    reinterpret_cast<uint2*>(dst)[idx] = pk;
}

// ---------------------------------------------------------------------------
// Prep: X transpose to fp16 [d][x] (B operand of out GEMM). Resets tile ctr.
// ---------------------------------------------------------------------------
__global__ __launch_bounds__(256) void transA_kernel(const float* __restrict__ X) {
    __shared__ float s[32][33];
    if (blockIdx.x == 0 && blockIdx.y == 0 && blockIdx.z == 0 &&
        threadIdx.x == 0 && threadIdx.y == 0) g_tile = 0u;
    int b = blockIdx.z;
    const float* in = X + (size_t)b * NX_ * D_;
    __half* out = g_XT + (size_t)b * D_ * NX_;
    int x0 = blockIdx.x * 32, d0 = blockIdx.y * 32;
    int tx = threadIdx.x, ty = threadIdx.y;
#pragma unroll
    for (int l = 0; l < 4; l++)
        s[ty + l * 8][tx] = in[(size_t)(x0 + ty + l * 8) * D_ + d0 + tx];
    __syncthreads();
#pragma unroll
    for (int l = 0; l < 4; l++)
        out[(size_t)(d0 + ty + l * 8) * NX_ + x0 + tx] = __float2half_rn(s[tx][ty + l * 8]);
}

// ---------------------------------------------------------------------------
// Tensor-core GEMM via mma.sync m16n8k16 (arch-agnostic HMMA path; tcgen05
// is unavailable at the harness's sm_103 PTX target).
// D[M][N](f32) = A[M][K](f16 row-major) @ B[N][K](f16, i.e. col-major KxN).
// CTA tile 128M x 64N, 4 warps (warp = 32M x 64N = 2x8 mma tiles), K chunk 64.
// smem rows padded to 72 halves -> ldmatrix conflict-free.
// mode 0 (proj): A=W[side] (M=h), B=Xh/refh[b] (N=x), C=fp16 hT + bias. K=256.
// mode 1 (out):  A=attn[b] (M=r), B=XT[b] (N=d),      C=fp32 out.       K=512.
// ---------------------------------------------------------------------------
#define SMS 72   // smem row stride in halves

__global__ __launch_bounds__(128) void mma_gemm_kernel(int mode,
                                                       const float* __restrict__ b_X,
                                                       const float* __restrict__ b_ref,
                                                       float* __restrict__ outp) {
    __shared__ __half sA[128 * SMS];   // 18 KB
    __shared__ __half sB[64 * SMS];    //  9 KB
    int tid = threadIdx.x, wid = tid >> 5, lane = tid & 31;
    int m0c = blockIdx.y * 128, n0c = blockIdx.x * 64;

    const __half *Ap, *Bp;
    __half* Ch = nullptr; float* Cf = nullptr; const float* bias = nullptr;
    int K;
    if (mode == 0) {
        int z = blockIdx.z, b = z & 7, side = z >> 3;
        Ap = g_Wh + (size_t)side * H_ * D_;
        Bp = (side ? g_refh : g_Xh) + (size_t)b * NX_ * D_;
        Ch = (side ? g_hRT : g_hXT) + (size_t)b * H_ * NX_;
        bias = side ? b_ref : b_X;
        K = D_;
    } else {
        int b = blockIdx.z;
        Ap = g_attn + (size_t)b * NR_ * NX_;
        Bp = g_XT + (size_t)b * D_ * NX_;
        Cf = outp + (size_t)b * NR_ * D_;
        K = NX_;
    }

    float acc[2][8][4] = {};

    // ldmatrix lane addressing
    int l8 = lane & 7;
    int a_row_off = l8 + ((lane >> 3) & 1) * 8;   // A: +row within 16
    int a_col_off = ((lane >> 4) & 1) * 8;        // A: +k
    int b_row_off = l8 + ((lane >> 4) & 1) * 8;   // B: +n within 16
    int b_col_off = ((lane >> 3) & 1) * 8;        // B: +k

    for (int k0 = 0; k0 < K; k0 += 64) {
        // fill A: 128 rows x 64 halves (8 uint4/row), 8 per thread
#pragma unroll
        for (int i = 0; i < 8; i++) {
            int idx = tid + i * 128;
            int row = idx >> 3, c = idx & 7;
            *reinterpret_cast<uint4*>(&sA[row * SMS + c * 8]) =
                *reinterpret_cast<const uint4*>(Ap + (size_t)(m0c + row) * K + k0 + c * 8);
        }
        // fill B: 64 rows x 64 halves, 4 per thread
#pragma unroll
        for (int i = 0; i < 4; i++) {
            int idx = tid + i * 128;
            int row = idx >> 3, c = idx & 7;
            *reinterpret_cast<uint4*>(&sB[row * SMS + c * 8]) =
                *reinterpret_cast<const uint4*>(Bp + (size_t)(n0c + row) * K + k0 + c * 8);
        }
        __syncthreads();

#pragma unroll
        for (int ks = 0; ks < 64; ks += 16) {
            unsigned a[2][4];
#pragma unroll
            for (int mt = 0; mt < 2; mt++) {
                int mb = wid * 32 + mt * 16;
                unsigned addr = smem_u32(&sA[(mb + a_row_off) * SMS + ks + a_col_off]);
                LDSM_X4(a[mt][0], a[mt][1], a[mt][2], a[mt][3], addr);
            }
#pragma unroll
            for (int ng = 0; ng < 4; ng++) {          // n-groups of 16
                int nb = ng * 16;
                unsigned b0, b1, b2, b3;
                unsigned addr = smem_u32(&sB[(nb + b_row_off) * SMS + ks + b_col_off]);
                LDSM_X4(b0, b1, b2, b3, addr);
                unsigned bA[2] = {b0, b1};            // n tile nb
                unsigned bB[2] = {b2, b3};            // n tile nb+8
#pragma unroll
                for (int mt = 0; mt < 2; mt++) {
                    MMA16816(acc[mt][2 * ng + 0], a[mt], bA);
                    MMA16816(acc[mt][2 * ng + 1], a[mt], bB);
                }
            }
        }
        __syncthreads();
    }

    // epilogue: thread owns (row = m0c+wid*32+mt*16+lane/4 [+8], col = n0c+nt*8+2*(lane%4))
    int rbase = m0c + wid * 32 + (lane >> 2);
    int cbase = n0c + 2 * (lane & 3);
#pragma unroll
    for (int mt = 0; mt < 2; mt++) {
        int r0 = rbase + mt * 16;
        if (mode == 0) {
            float bb0 = bias[r0], bb1 = bias[r0 + 8];
#pragma unroll
            for (int nt = 0; nt < 8; nt++) {
                float* c = acc[mt][nt];
                int col = cbase + nt * 8;
                __half2 h0 = __floats2half2_rn(c[0] + bb0, c[1] + bb0);
                __half2 h1 = __floats2half2_rn(c[2] + bb1, c[3] + bb1);
                *reinterpret_cast<unsigned*>(&Ch[(size_t)r0 * NX_ + col]) =
                    *reinterpret_cast<unsigned*>(&h0);
                *reinterpret_cast<unsigned*>(&Ch[(size_t)(r0 + 8) * NX_ + col]) =
                    *reinterpret_cast<unsigned*>(&h1);
            }
        } else {
#pragma unroll
            for (int nt = 0; nt < 8; nt++) {
                float* c = acc[mt][nt];
                int col = cbase + nt * 8;
                float2 o0 = {c[0], c[1]}, o1 = {c[2], c[3]};
                *reinterpret_cast<float2*>(&Cf[(size_t)r0 * D_ + col]) = o0;
                *reinterpret_cast<float2*>(&Cf[(size_t)(r0 + 8) * D_ + col]) = o1;
            }
        }
    }
}

// ---------------------------------------------------------------------------
// Score: g_S[b][r][x] = exp( sum_h v[h]*tanh(hX[b][h][x] + hR[b][h][r]) )
// Persistent 444 CTAs, 64x * 32r tiles. Arithmetic identical to R14; store is
// row-major [r][x] (exp fused; bounded scores -> max-free softmax fp32-safe).
// ---------------------------------------------------------------------------
#define NTILES      1024
#define SCORE_CTAS  444

__device__ __forceinline__ __half2 tanh2(__half2 x) {
    __half2 y;
    asm("tanh.approx.f16x2 %0, %1;"
        : "=r"(*reinterpret_cast<unsigned*>(&y))
        : "r"(*reinterpret_cast<unsigned*>(&x)));
    return y;
}

__global__ __launch_bounds__(256) void score_kernel(const float* __restrict__ vw) {
    __shared__ __half2  sX2[32][64];
    __shared__ __half   sR [32][32];
    __shared__ __half2  sv2[H_];
    __shared__ unsigned s_tile;

    int tid = threadIdx.x;
    int tx = tid & 15, ty = tid >> 4;
    int frow = tid >> 3, fseg = tid & 7;

    sv2[tid] = __half2half2(__float2half_rn(vw[tid]));

    for (;;) {
        __syncthreads();
        if (tid == 0) s_tile = atomicAdd(&g_tile, 1u);
        __syncthreads();
        unsigned t = s_tile;
        if (t >= NTILES) break;
        int b  = (int)(t >> 7);
        int r0 = (int)((t >> 3) & 15) * 32;
        int x0 = (int)(t & 7) * 64;
        const __half* hXb = g_hXT + (size_t)b * H_ * NX_;
        const __half* hRb = g_hRT + (size_t)b * H_ * NR_;

        float acc[4][2] = {};

        for (int h0 = 0; h0 < H_; h0 += 32) {
            uint4 xv = *reinterpret_cast<const uint4*>(&hXb[(size_t)(h0 + frow) * NX_ + x0 + fseg * 8]);
            const __half* xh = reinterpret_cast<const __half*>(&xv);
            __half2* dst = &sX2[frow][fseg * 8];
#pragma unroll
            for (int k = 0; k < 8; k++) dst[k] = __half2half2(xh[k]);
            *reinterpret_cast<uint2*>(&sR[frow][fseg * 4]) =
                *reinterpret_cast<const uint2*>(&hRb[(size_t)(h0 + frow) * NR_ + r0 + fseg * 4]);
            __syncthreads();

#pragma unroll
            for (int hh = 0; hh < 32; hh += 8) {
                __half2 a2[4] = {};
#pragma unroll
                for (int h = 0; h < 8; h++) {
                    int hc = hh + h;
                    __half2 v2 = sv2[h0 + hc];
                    uint4 xu = *reinterpret_cast<const uint4*>(&sX2[hc][ty * 4]);
                    __half2 rr = *reinterpret_cast<const __half2*>(&sR[hc][tx * 2]);
                    __half2 x2[4] = {*reinterpret_cast<__half2*>(&xu.x),
                                     *reinterpret_cast<__half2*>(&xu.y),
                                     *reinterpret_cast<__half2*>(&xu.z),
                                     *reinterpret_cast<__half2*>(&xu.w)};
#pragma unroll
                    for (int i = 0; i < 4; i++)
                        a2[i] = __hfma2(v2, tanh2(__hadd2(x2[i], rr)), a2[i]);
                }
#pragma unroll
                for (int i = 0; i < 4; i++) {
                    float2 f = __half22float2(a2[i]);
                    acc[i][0] += f.x;
                    acc[i][1] += f.y;
                }
            }
            __syncthreads();
        }

        float* Sb = g_S + (size_t)b * NR_ * NX_;
        int rr0 = r0 + tx * 2;
        float4 o0 = {__expf(acc[0][0]), __expf(acc[1][0]), __expf(acc[2][0]), __expf(acc[3][0])};
        float4 o1 = {__expf(acc[0][1]), __expf(acc[1][1]), __expf(acc[2][1]), __expf(acc[3][1])};
        *reinterpret_cast<float4*>(&Sb[(size_t)rr0 * NX_ + x0 + ty * 4]) = o0;
        *reinterpret_cast<float4*>(&Sb[(size_t)(rr0 + 1) * NX_ + x0 + ty * 4]) = o1;
    }
}

// ---------------------------------------------------------------------------
// Row softmax finalize: attn[b][r][x] = S[row][x] / sum_x S[row][x], fp16 out.
// ---------------------------------------------------------------------------
__global__ __launch_bounds__(128) void rowsoft_kernel() {
    int row = blockIdx.x;
    const float* p = g_S + (size_t)row * NX_;
    int t = threadIdx.x, w = t >> 5, lane = t & 31;

    float4 v = reinterpret_cast<const float4*>(p)[t];
    float s = v.x + v.y + v.z + v.w;
#pragma unroll
    for (int o = 16; o > 0; o >>= 1) s += __shfl_xor_sync(0xffffffffu, s, o);
    __shared__ float ss[4];
    if (lane == 0) ss[w] = s;
    __syncthreads();
    float inv = 1.0f / (ss[0] + ss[1] + ss[2] + ss[3]);

    __half2 h0 = __floats2half2_rn(v.x * inv, v.y * inv);
    __half2 h1 = __floats2half2_rn(v.z * inv, v.w * inv);
    uint2 pk = {*reinterpret_cast<unsigned*>(&h0), *reinterpret_cast<unsigned*>(&h1)};
    reinterpret_cast<uint2*>(g_attn + (size_t)row * NX_)[t] = pk;
}

// ---------------------------------------------------------------------------
// Launch (graph-capturable, allocation-free). Device globals are resolved
// inside kernels only.
// Inputs: X, ref, W_X, b_X, W_ref, b_ref, v_w, v_b (v_b drops out of softmax).
// ---------------------------------------------------------------------------
extern "C" void kernel_launch(void* const* d_in, const int* in_sizes, int n_in,
                              void* d_out, int out_size) {
    const float* X     = (const float*)d_in[0];
    const float* ref   = (const float*)d_in[1];
    const float* W_X   = (const float*)d_in[2];
    const float* b_X   = (const float*)d_in[3];
    const float* W_ref = (const float*)d_in[4];
    const float* b_ref = (const float*)d_in[5];
    const float* v_w   = (const float*)d_in[6];
    float* out = (float*)d_out;

    dim3 blk(256);
    f2h_kernel<<<(B_ * NX_ * D_ / 4) / 256, blk>>>(X,   0);
    f2h_kernel<<<(B_ * NR_ * D_ / 4) / 256, blk>>>(ref, 1);
    f2h_kernel<<<(H_ * D_ / 4) / 256, blk>>>(W_X,   2);
    f2h_kernel<<<(H_ * D_ / 4) / 256, blk>>>(W_ref, 3);
    transA_kernel<<<dim3(NX_ / 32, D_ / 32, B_), dim3(32, 8)>>>(X);

    // proj: M=H(256)->grid.y=2, N=NX(512)->grid.x=8, z=2*B
    mma_gemm_kernel<<<dim3(NX_ / 64, H_ / 128, 2 * B_), 128>>>(0, b_X, b_ref, nullptr);
    score_kernel<<<SCORE_CTAS, blk>>>(v_w);
    rowsoft_kernel<<<B_ * NR_, 128>>>();
    // out: M=NR(512)->grid.y=4, N=D(256)->grid.x=4, z=B
    mma_gemm_kernel<<<dim3(D_ / 64, NR_ / 128, B_), 128>>>(1, nullptr, nullptr, out);
}